// round 2
// baseline (speedup 1.0000x reference)
#include <cuda_runtime.h>
#include <math.h>

#define NRES 512
#define CS 384
#define CZ 128
#define CH 16
#define NH 12
#define PQ 4
#define PV 8

// ---------------- device scratch (static allocation only) ----------------
__device__ __align__(16) float g_q[NRES * NH * CH];            // [i][h][c]
__device__ __align__(16) float g_kT[NH * NRES * CH];           // [h][j][c]
__device__ __align__(16) float g_v[NRES * NH * CH];            // [j][h][c]
__device__ __align__(16) float g_qpts[NRES * NH * PQ * 3];     // [i][h][p][d]
__device__ __align__(16) float g_kptsT[NH * NRES * PQ * 3];    // [h][j][p][d]
__device__ __align__(16) float g_vpts[NRES * NH * PV * 3];     // [j][h][p][d]
__device__ __align__(16) float g_bias[NRES * NRES * NH];       // [i][j][h]
__device__ __align__(16) float g_a[NH * NRES * NRES];          // [h][i][j]
__device__ __align__(16) float g_opt[NRES * NH * PV * 3];      // [i][h][p][d] (global frame)
__device__ __align__(16) float g_cat[NRES * 2112];             // concat features
__device__ float g_hw[NH];

// ---------------- kernel A: projections + frame transform ----------------
__global__ void k_proj(const float* __restrict__ s, const float* __restrict__ rot,
                       const float* __restrict__ trans,
                       const float* __restrict__ Wq, const float* __restrict__ bq,
                       const float* __restrict__ Wkv, const float* __restrict__ bkv,
                       const float* __restrict__ Wqp, const float* __restrict__ bqp,
                       const float* __restrict__ Wkvp, const float* __restrict__ bkvp,
                       const float* __restrict__ hwts) {
    int i = blockIdx.x;
    int tid = threadIdx.x;  // 256
    __shared__ float s_sh[CS];
    __shared__ float praw[576];  // 144 (qp) + 432 (kvp)

    for (int t = tid; t < CS; t += 256) s_sh[t] = s[i * CS + t];
    if (i == 0 && tid < NH) {
        float x = hwts[tid];
        float sp = (x > 20.f) ? x : log1pf(expf(x));
        g_hw[tid] = sp * 0.13608276348795434f;  // sqrt(1/54)
    }
    __syncthreads();

    // 288 float4-column jobs: q(48) kv(96) qp(36) kvp(108)
    for (int job = tid; job < 288; job += 256) {
        int col4 = job * 4;
        const float* W; const float* bv; int outw; int c;
        if (col4 < 192)      { W = Wq;   bv = bq;   outw = 192; c = col4; }
        else if (col4 < 576) { W = Wkv;  bv = bkv;  outw = 384; c = col4 - 192; }
        else if (col4 < 720) { W = Wqp;  bv = bqp;  outw = 144; c = col4 - 576; }
        else                 { W = Wkvp; bv = bkvp; outw = 432; c = col4 - 720; }
        float4 acc = make_float4(0.f, 0.f, 0.f, 0.f);
        #pragma unroll 4
        for (int k = 0; k < CS; k++) {
            float sv = s_sh[k];
            float4 w = *(const float4*)&W[k * outw + c];
            acc.x += sv * w.x; acc.y += sv * w.y;
            acc.z += sv * w.z; acc.w += sv * w.w;
        }
        acc.x += bv[c]; acc.y += bv[c + 1]; acc.z += bv[c + 2]; acc.w += bv[c + 3];
        float vals[4] = {acc.x, acc.y, acc.z, acc.w};
        #pragma unroll
        for (int u = 0; u < 4; u++) {
            int gc = col4 + u; float val = vals[u];
            if (gc < 192) {
                g_q[i * 192 + gc] = val;
            } else if (gc < 576) {
                int cc = gc - 192; int h = cc / 32; int r = cc % 32;
                if (r < 16) g_kT[h * (NRES * CH) + i * CH + r] = val;
                else        g_v[i * 192 + h * CH + (r - 16)] = val;
            } else if (gc < 720) {
                praw[gc - 576] = val;
            } else {
                praw[144 + (gc - 720)] = val;
            }
        }
    }
    __syncthreads();

    if (tid < 192) {
        float R[9], T[3];
        #pragma unroll
        for (int d = 0; d < 9; d++) R[d] = rot[i * 9 + d];
        #pragma unroll
        for (int d = 0; d < 3; d++) T[d] = trans[i * 3 + d];
        if (tid < 48) {  // q points: h in 0..11, p in 0..3
            int h = tid / 4, p = tid % 4;
            float pl[3];
            #pragma unroll
            for (int d = 0; d < 3; d++) pl[d] = praw[d * 48 + h * 4 + p];
            #pragma unroll
            for (int d = 0; d < 3; d++) {
                float g = R[d * 3 + 0] * pl[0] + R[d * 3 + 1] * pl[1] + R[d * 3 + 2] * pl[2] + T[d];
                g_qpts[i * 144 + h * 12 + p * 3 + d] = g;
            }
        } else {         // kv points: h in 0..11, pp in 0..11
            int idx = tid - 48; int h = idx / 12, pp = idx % 12;
            float pl[3];
            #pragma unroll
            for (int d = 0; d < 3; d++) pl[d] = praw[144 + d * 144 + h * 12 + pp];
            #pragma unroll
            for (int d = 0; d < 3; d++) {
                float g = R[d * 3 + 0] * pl[0] + R[d * 3 + 1] * pl[1] + R[d * 3 + 2] * pl[2] + T[d];
                if (pp < 4) g_kptsT[h * (NRES * 12) + i * 12 + pp * 3 + d] = g;
                else        g_vpts[i * 288 + h * 24 + (pp - 4) * 3 + d] = g;
            }
        }
    }
}

// ---------------- kernel B1: bias = z @ Wb (warp per row) ----------------
__global__ void k_bias(const float* __restrict__ z, const float* __restrict__ Wb) {
    int lane = threadIdx.x & 31;
    int wid = threadIdx.x >> 5;
    int warp_global = blockIdx.x * 8 + wid;
    int nwarps = gridDim.x * 8;
    float w[4][12];
    #pragma unroll
    for (int u = 0; u < 4; u++)
        #pragma unroll
        for (int h = 0; h < 12; h++) w[u][h] = Wb[(lane * 4 + u) * 12 + h];
    for (int row = warp_global; row < NRES * NRES; row += nwarps) {
        float4 zv = *(const float4*)&z[(size_t)row * CZ + lane * 4];
        float p[12];
        #pragma unroll
        for (int h = 0; h < 12; h++)
            p[h] = zv.x * w[0][h] + zv.y * w[1][h] + zv.z * w[2][h] + zv.w * w[3][h];
        #pragma unroll
        for (int off = 16; off > 0; off >>= 1)
            #pragma unroll
            for (int h = 0; h < 12; h++)
                p[h] += __shfl_xor_sync(0xffffffffu, p[h], off);
        if (lane < 12) g_bias[row * 12 + lane] = p[lane];
    }
}

// ---------------- kernel B2: attention logits ----------------
__global__ void k_logits(const float* __restrict__ bb, const float* __restrict__ mask) {
    int i = blockIdx.x, h = blockIdx.y;
    int tid = threadIdx.x;  // 256
    float q[16], qp[12];
    #pragma unroll
    for (int c = 0; c < 16; c++) q[c] = g_q[i * 192 + h * 16 + c];
    #pragma unroll
    for (int t = 0; t < 12; t++) qp[t] = g_qpts[i * 144 + h * 12 + t];
    float hw = g_hw[h];
    float bbh = bb[h];
    float mi = mask[i];
    const float C1 = 0.14433756729740643f;  // sqrt(1/48)
    const float C2 = 0.5773502691896258f;   // sqrt(1/3)
    for (int j = tid; j < NRES; j += 256) {
        const float* kr = &g_kT[h * (NRES * CH) + j * CH];
        float qk = 0.f;
        #pragma unroll
        for (int c = 0; c < 16; c++) qk += q[c] * kr[c];
        const float* kp = &g_kptsT[h * (NRES * 12) + j * 12];
        float d2 = 0.f;
        #pragma unroll
        for (int t = 0; t < 12; t++) { float dd = qp[t] - kp[t]; d2 += dd * dd; }
        float bias = g_bias[(i * NRES + j) * 12 + h] + bbh;
        float mj = mask[j];
        g_a[(h * NRES + i) * NRES + j] =
            qk * C1 + C2 * bias - 0.5f * hw * d2 + 100000.0f * (mi * mj - 1.0f);
    }
}

// ---------------- kernel C: softmax over j ----------------
__global__ void k_softmax() {
    int row = blockIdx.x;  // 6144 = H*N
    float* a = &g_a[(size_t)row * NRES];
    int tid = threadIdx.x;  // 256
    int lane = tid & 31, wid = tid >> 5;
    __shared__ float redm[8];
    __shared__ float reds[8];
    float v0 = a[tid], v1 = a[tid + 256];
    float m = fmaxf(v0, v1);
    #pragma unroll
    for (int off = 16; off > 0; off >>= 1) m = fmaxf(m, __shfl_xor_sync(0xffffffffu, m, off));
    if (lane == 0) redm[wid] = m;
    __syncthreads();
    if (tid == 0) {
        float mm = redm[0];
        #pragma unroll
        for (int r = 1; r < 8; r++) mm = fmaxf(mm, redm[r]);
        redm[0] = mm;
    }
    __syncthreads();
    float mm = redm[0];
    v0 = expf(v0 - mm); v1 = expf(v1 - mm);
    float s = v0 + v1;
    #pragma unroll
    for (int off = 16; off > 0; off >>= 1) s += __shfl_xor_sync(0xffffffffu, s, off);
    if (lane == 0) reds[wid] = s;
    __syncthreads();
    if (tid == 0) {
        float ss = reds[0];
        #pragma unroll
        for (int r = 1; r < 8; r++) ss += reds[r];
        reds[0] = ss;
    }
    __syncthreads();
    float inv = 1.0f / reds[0];
    a[tid] = v0 * inv;
    a[tid + 256] = v1 * inv;
}

// ---------------- kernel D: apply attention (o, o_pt, o_pair) ----------------
__global__ void k_att_apply(const float* __restrict__ z) {
    int i = blockIdx.x;
    int tid = threadIdx.x;  // 384
    __shared__ float a_sh[NH * NRES];      // 24 KB
    __shared__ float op_acc[NH * CZ];      // 6 KB
    for (int idx = tid; idx < NH * NRES; idx += 384) {
        int h = idx >> 9, j = idx & 511;
        a_sh[idx] = g_a[((size_t)h * NRES + i) * NRES + j];
    }
    for (int idx = tid; idx < NH * CZ; idx += 384) op_acc[idx] = 0.f;
    __syncthreads();

    if (tid < 256) {
        // o_pair: 8 j-subgroups x 32 channel-groups (4 ch each)
        int sub = tid >> 5;
        int cg = tid & 31;
        float4 acc[12];
        #pragma unroll
        for (int h = 0; h < 12; h++) acc[h] = make_float4(0.f, 0.f, 0.f, 0.f);
        for (int j = sub; j < NRES; j += 8) {
            float4 zv = *(const float4*)&z[((size_t)i * NRES + j) * CZ + cg * 4];
            #pragma unroll
            for (int h = 0; h < 12; h++) {
                float av = a_sh[h * NRES + j];
                acc[h].x += av * zv.x; acc[h].y += av * zv.y;
                acc[h].z += av * zv.z; acc[h].w += av * zv.w;
            }
        }
        #pragma unroll
        for (int h = 0; h < 12; h++) {
            atomicAdd(&op_acc[h * CZ + cg * 4 + 0], acc[h].x);
            atomicAdd(&op_acc[h * CZ + cg * 4 + 1], acc[h].y);
            atomicAdd(&op_acc[h * CZ + cg * 4 + 2], acc[h].z);
            atomicAdd(&op_acc[h * CZ + cg * 4 + 3], acc[h].w);
        }
    } else if (tid < 304) {
        // o: 48 threads x 4 channels = 192
        int ch4 = (tid - 256) * 4;
        int h = ch4 >> 4;
        float4 acc = make_float4(0.f, 0.f, 0.f, 0.f);
        for (int j = 0; j < NRES; j++) {
            float4 vv = *(const float4*)&g_v[j * 192 + ch4];
            float av = a_sh[h * NRES + j];
            acc.x += av * vv.x; acc.y += av * vv.y;
            acc.z += av * vv.z; acc.w += av * vv.w;
        }
        *(float4*)&g_cat[i * 2112 + ch4] = acc;
    } else if (tid < 376) {
        // o_pt (global frame): 72 threads x 4 channels = 288
        int ch4 = (tid - 304) * 4;
        int h = ch4 / 24;
        float4 acc = make_float4(0.f, 0.f, 0.f, 0.f);
        for (int j = 0; j < NRES; j++) {
            float4 pv = *(const float4*)&g_vpts[j * 288 + ch4];
            float av = a_sh[h * NRES + j];
            acc.x += av * pv.x; acc.y += av * pv.y;
            acc.z += av * pv.z; acc.w += av * pv.w;
        }
        *(float4*)&g_opt[i * 288 + ch4] = acc;
    }
    __syncthreads();
    for (int idx = tid; idx < NH * CZ; idx += 384)
        g_cat[i * 2112 + 576 + idx] = op_acc[idx];
}

// ---------------- kernel D3: inverse frame + norms ----------------
__global__ void k_rot_back(const float* __restrict__ rot, const float* __restrict__ trans) {
    int i = blockIdx.x;
    int r = threadIdx.x;  // 0..95 = h*8+p
    float g0 = g_opt[i * 288 + r * 3 + 0] - trans[i * 3 + 0];
    float g1 = g_opt[i * 288 + r * 3 + 1] - trans[i * 3 + 1];
    float g2 = g_opt[i * 288 + r * 3 + 2] - trans[i * 3 + 2];
    float lx = rot[i * 9 + 0] * g0 + rot[i * 9 + 3] * g1 + rot[i * 9 + 6] * g2;
    float ly = rot[i * 9 + 1] * g0 + rot[i * 9 + 4] * g1 + rot[i * 9 + 7] * g2;
    float lz = rot[i * 9 + 2] * g0 + rot[i * 9 + 5] * g1 + rot[i * 9 + 8] * g2;
    float nrm = sqrtf(lx * lx + ly * ly + lz * lz + 1e-8f);
    g_cat[i * 2112 + 192 + r] = lx;
    g_cat[i * 2112 + 288 + r] = ly;
    g_cat[i * 2112 + 384 + r] = lz;
    g_cat[i * 2112 + 480 + r] = nrm;
}

// ---------------- kernel E: out = cat @ Wout + bout ----------------
__global__ void k_out(const float* __restrict__ Wout, const float* __restrict__ bout,
                      float* __restrict__ out) {
    // grid (128, 3), block 128: 4 rows x 128 cols per block
    int i0 = blockIdx.x * 4;
    int oc0 = blockIdx.y * 128;
    __shared__ float cat_sh[4][2112];  // ~33 KB
    int tid = threadIdx.x;
    for (int idx = tid; idx < 4 * 2112; idx += 128) {
        int r = idx / 2112, k = idx % 2112;
        cat_sh[r][k] = g_cat[(i0 + r) * 2112 + k];
    }
    __syncthreads();
    int rg = tid >> 5, cg = tid & 31;
    int col = oc0 + cg * 4;
    float4 acc = *(const float4*)&bout[col];
    const float* ws = &Wout[col];
    #pragma unroll 4
    for (int k = 0; k < 2112; k++) {
        float4 w = *(const float4*)&ws[k * 384];
        float a = cat_sh[rg][k];
        acc.x += a * w.x; acc.y += a * w.y;
        acc.z += a * w.z; acc.w += a * w.w;
    }
    *(float4*)&out[(i0 + rg) * 384 + col] = acc;
}

extern "C" void kernel_launch(void* const* d_in, const int* in_sizes, int n_in,
                              void* d_out, int out_size) {
    const float* s     = (const float*)d_in[0];
    const float* z     = (const float*)d_in[1];
    const float* rot   = (const float*)d_in[2];
    const float* trans = (const float*)d_in[3];
    const float* mask  = (const float*)d_in[4];
    const float* Wq    = (const float*)d_in[5];
    const float* bq    = (const float*)d_in[6];
    const float* Wkv   = (const float*)d_in[7];
    const float* bkv   = (const float*)d_in[8];
    const float* Wqp   = (const float*)d_in[9];
    const float* bqp   = (const float*)d_in[10];
    const float* Wkvp  = (const float*)d_in[11];
    const float* bkvp  = (const float*)d_in[12];
    const float* Wb    = (const float*)d_in[13];
    const float* bb    = (const float*)d_in[14];
    const float* hwts  = (const float*)d_in[15];
    const float* Wout  = (const float*)d_in[16];
    const float* bout  = (const float*)d_in[17];
    float* out = (float*)d_out;

    k_proj<<<NRES, 256>>>(s, rot, trans, Wq, bq, Wkv, bkv, Wqp, bqp, Wkvp, bkvp, hwts);
    k_bias<<<2048, 256>>>(z, Wb);
    k_logits<<<dim3(NRES, NH), 256>>>(bb, mask);
    k_softmax<<<NH * NRES, 256>>>();
    k_att_apply<<<NRES, 384>>>(z);
    k_rot_back<<<NRES, 96>>>(rot, trans);
    k_out<<<dim3(128, 3), 128>>>(Wout, bout, out);
}

// round 4
// speedup vs baseline: 1.0230x; 1.0230x over previous
#include <cuda_runtime.h>
#include <math.h>

#define NRES 512
#define CS 384
#define CZ 128
#define CH 16
#define NH 12
#define PQ 4
#define PV 8

// ---------------- device scratch (static allocation only) ----------------
__device__ __align__(16) float g_q[NRES * NH * CH];            // [i][h][c]
__device__ __align__(16) float g_kT[NH * NRES * CH];           // [h][j][c]
__device__ __align__(16) float g_v[NRES * NH * CH];            // [j][h][c]
__device__ __align__(16) float g_qpts[NRES * NH * PQ * 3];     // [i][h][p][d]
__device__ __align__(16) float g_kptsT[NH * NRES * PQ * 3];    // [h][j][p][d]
__device__ __align__(16) float g_vpts[NRES * NH * PV * 3];     // [j][h][p][d]
__device__ __align__(16) float g_bias[NRES * NRES * NH];       // [i][j][h]
__device__ __align__(16) float g_a[NH * NRES * NRES];          // [h][i][j]
__device__ __align__(16) float g_opt[NRES * NH * PV * 3];      // [i][h][p][d] (global frame)
__device__ __align__(16) float g_cat[NRES * 2112];             // concat features
__device__ float g_hw[NH];

// ---------------- kernel A: projections + frame transform ----------------
__global__ void k_proj(const float* __restrict__ s, const float* __restrict__ rot,
                       const float* __restrict__ trans,
                       const float* __restrict__ Wq, const float* __restrict__ bq,
                       const float* __restrict__ Wkv, const float* __restrict__ bkv,
                       const float* __restrict__ Wqp, const float* __restrict__ bqp,
                       const float* __restrict__ Wkvp, const float* __restrict__ bkvp,
                       const float* __restrict__ hwts) {
    int i = blockIdx.x;
    int tid = threadIdx.x;  // 256
    __shared__ float s_sh[CS];
    __shared__ float praw[576];  // 144 (qp) + 432 (kvp)

    for (int t = tid; t < CS; t += 256) s_sh[t] = s[i * CS + t];
    if (i == 0 && tid < NH) {
        float x = hwts[tid];
        float sp = (x > 20.f) ? x : log1pf(expf(x));
        g_hw[tid] = sp * 0.13608276348795434f;  // sqrt(1/54)
    }
    __syncthreads();

    // 288 float4-column jobs: q(48) kv(96) qp(36) kvp(108)
    for (int job = tid; job < 288; job += 256) {
        int col4 = job * 4;
        const float* W; const float* bv; int outw; int c;
        if (col4 < 192)      { W = Wq;   bv = bq;   outw = 192; c = col4; }
        else if (col4 < 576) { W = Wkv;  bv = bkv;  outw = 384; c = col4 - 192; }
        else if (col4 < 720) { W = Wqp;  bv = bqp;  outw = 144; c = col4 - 576; }
        else                 { W = Wkvp; bv = bkvp; outw = 432; c = col4 - 720; }
        float4 acc = make_float4(0.f, 0.f, 0.f, 0.f);
        #pragma unroll 4
        for (int k = 0; k < CS; k++) {
            float sv = s_sh[k];
            float4 w = *(const float4*)&W[k * outw + c];
            acc.x += sv * w.x; acc.y += sv * w.y;
            acc.z += sv * w.z; acc.w += sv * w.w;
        }
        acc.x += bv[c]; acc.y += bv[c + 1]; acc.z += bv[c + 2]; acc.w += bv[c + 3];
        float vals[4] = {acc.x, acc.y, acc.z, acc.w};
        #pragma unroll
        for (int u = 0; u < 4; u++) {
            int gc = col4 + u; float val = vals[u];
            if (gc < 192) {
                g_q[i * 192 + gc] = val;
            } else if (gc < 576) {
                int cc = gc - 192; int h = cc / 32; int r = cc % 32;
                if (r < 16) g_kT[h * (NRES * CH) + i * CH + r] = val;
                else        g_v[i * 192 + h * CH + (r - 16)] = val;
            } else if (gc < 720) {
                praw[gc - 576] = val;
            } else {
                praw[144 + (gc - 720)] = val;
            }
        }
    }
    __syncthreads();

    if (tid < 192) {
        float R[9], T[3];
        #pragma unroll
        for (int d = 0; d < 9; d++) R[d] = rot[i * 9 + d];
        #pragma unroll
        for (int d = 0; d < 3; d++) T[d] = trans[i * 3 + d];
        if (tid < 48) {  // q points: h in 0..11, p in 0..3
            int h = tid / 4, p = tid % 4;
            float pl[3];
            #pragma unroll
            for (int d = 0; d < 3; d++) pl[d] = praw[d * 48 + h * 4 + p];
            #pragma unroll
            for (int d = 0; d < 3; d++) {
                float g = R[d * 3 + 0] * pl[0] + R[d * 3 + 1] * pl[1] + R[d * 3 + 2] * pl[2] + T[d];
                g_qpts[i * 144 + h * 12 + p * 3 + d] = g;
            }
        } else {         // kv points: h in 0..11, pp in 0..11
            int idx = tid - 48; int h = idx / 12, pp = idx % 12;
            float pl[3];
            #pragma unroll
            for (int d = 0; d < 3; d++) pl[d] = praw[144 + d * 144 + h * 12 + pp];
            #pragma unroll
            for (int d = 0; d < 3; d++) {
                float g = R[d * 3 + 0] * pl[0] + R[d * 3 + 1] * pl[1] + R[d * 3 + 2] * pl[2] + T[d];
                if (pp < 4) g_kptsT[h * (NRES * 12) + i * 12 + pp * 3 + d] = g;
                else        g_vpts[i * 288 + h * 24 + (pp - 4) * 3 + d] = g;
            }
        }
    }
}

// ---------------- kernel B1: bias = z @ Wb (warp per row) ----------------
__global__ void k_bias(const float* __restrict__ z, const float* __restrict__ Wb) {
    int lane = threadIdx.x & 31;
    int wid = threadIdx.x >> 5;
    int warp_global = blockIdx.x * 8 + wid;
    int nwarps = gridDim.x * 8;
    float w[4][12];
    #pragma unroll
    for (int u = 0; u < 4; u++)
        #pragma unroll
        for (int h = 0; h < 12; h++) w[u][h] = Wb[(lane * 4 + u) * 12 + h];
    for (int row = warp_global; row < NRES * NRES; row += nwarps) {
        float4 zv = *(const float4*)&z[(size_t)row * CZ + lane * 4];
        float p[12];
        #pragma unroll
        for (int h = 0; h < 12; h++)
            p[h] = zv.x * w[0][h] + zv.y * w[1][h] + zv.z * w[2][h] + zv.w * w[3][h];
        #pragma unroll
        for (int off = 16; off > 0; off >>= 1)
            #pragma unroll
            for (int h = 0; h < 12; h++)
                p[h] += __shfl_xor_sync(0xffffffffu, p[h], off);
        if (lane < 12) g_bias[row * 12 + lane] = p[lane];
    }
}

// ---------------- kernel B2: attention logits ----------------
__global__ void k_logits(const float* __restrict__ bb, const float* __restrict__ mask) {
    int i = blockIdx.x, h = blockIdx.y;
    int tid = threadIdx.x;  // 256
    float q[16], qp[12];
    #pragma unroll
    for (int c = 0; c < 16; c++) q[c] = g_q[i * 192 + h * 16 + c];
    #pragma unroll
    for (int t = 0; t < 12; t++) qp[t] = g_qpts[i * 144 + h * 12 + t];
    float hw = g_hw[h];
    float bbh = bb[h];
    float mi = mask[i];
    const float C1 = 0.14433756729740643f;  // sqrt(1/48)
    const float C2 = 0.5773502691896258f;   // sqrt(1/3)
    for (int j = tid; j < NRES; j += 256) {
        const float* kr = &g_kT[h * (NRES * CH) + j * CH];
        float qk = 0.f;
        #pragma unroll
        for (int c = 0; c < 16; c++) qk += q[c] * kr[c];
        const float* kp = &g_kptsT[h * (NRES * 12) + j * 12];
        float d2 = 0.f;
        #pragma unroll
        for (int t = 0; t < 12; t++) { float dd = qp[t] - kp[t]; d2 += dd * dd; }
        float bias = g_bias[(i * NRES + j) * 12 + h] + bbh;
        float mj = mask[j];
        g_a[(h * NRES + i) * NRES + j] =
            qk * C1 + C2 * bias - 0.5f * hw * d2 + 100000.0f * (mi * mj - 1.0f);
    }
}

// ---------------- kernel C: softmax over j ----------------
__global__ void k_softmax() {
    int row = blockIdx.x;  // 6144 = H*N
    float* a = &g_a[(size_t)row * NRES];
    int tid = threadIdx.x;  // 256
    int lane = tid & 31, wid = tid >> 5;
    __shared__ float redm[8];
    __shared__ float reds[8];
    float v0 = a[tid], v1 = a[tid + 256];
    float m = fmaxf(v0, v1);
    #pragma unroll
    for (int off = 16; off > 0; off >>= 1) m = fmaxf(m, __shfl_xor_sync(0xffffffffu, m, off));
    if (lane == 0) redm[wid] = m;
    __syncthreads();
    if (tid == 0) {
        float mm = redm[0];
        #pragma unroll
        for (int r = 1; r < 8; r++) mm = fmaxf(mm, redm[r]);
        redm[0] = mm;
    }
    __syncthreads();
    float mm = redm[0];
    v0 = expf(v0 - mm); v1 = expf(v1 - mm);
    float s = v0 + v1;
    #pragma unroll
    for (int off = 16; off > 0; off >>= 1) s += __shfl_xor_sync(0xffffffffu, s, off);
    if (lane == 0) reds[wid] = s;
    __syncthreads();
    if (tid == 0) {
        float ss = reds[0];
        #pragma unroll
        for (int r = 1; r < 8; r++) ss += reds[r];
        reds[0] = ss;
    }
    __syncthreads();
    float inv = 1.0f / reds[0];
    a[tid] = v0 * inv;
    a[tid + 256] = v1 * inv;
}

// ---------------- kernel D: apply attention (o, o_pt, o_pair) ----------------
__global__ void k_att_apply(const float* __restrict__ z) {
    int i = blockIdx.x;
    int tid = threadIdx.x;  // 384
    __shared__ float a_sh[NH * NRES];      // 24 KB
    __shared__ float op_acc[NH * CZ];      // 6 KB
    for (int idx = tid; idx < NH * NRES; idx += 384) {
        int h = idx >> 9, j = idx & 511;
        a_sh[idx] = g_a[((size_t)h * NRES + i) * NRES + j];
    }
    for (int idx = tid; idx < NH * CZ; idx += 384) op_acc[idx] = 0.f;
    __syncthreads();

    if (tid < 256) {
        // o_pair: 8 j-subgroups x 32 channel-groups (4 ch each)
        int sub = tid >> 5;
        int cg = tid & 31;
        float4 acc[12];
        #pragma unroll
        for (int h = 0; h < 12; h++) acc[h] = make_float4(0.f, 0.f, 0.f, 0.f);
        for (int j = sub; j < NRES; j += 8) {
            float4 zv = *(const float4*)&z[((size_t)i * NRES + j) * CZ + cg * 4];
            #pragma unroll
            for (int h = 0; h < 12; h++) {
                float av = a_sh[h * NRES + j];
                acc[h].x += av * zv.x; acc[h].y += av * zv.y;
                acc[h].z += av * zv.z; acc[h].w += av * zv.w;
            }
        }
        #pragma unroll
        for (int h = 0; h < 12; h++) {
            atomicAdd(&op_acc[h * CZ + cg * 4 + 0], acc[h].x);
            atomicAdd(&op_acc[h * CZ + cg * 4 + 1], acc[h].y);
            atomicAdd(&op_acc[h * CZ + cg * 4 + 2], acc[h].z);
            atomicAdd(&op_acc[h * CZ + cg * 4 + 3], acc[h].w);
        }
    } else if (tid < 304) {
        // o: 48 threads x 4 channels = 192
        int ch4 = (tid - 256) * 4;
        int h = ch4 >> 4;
        float4 acc = make_float4(0.f, 0.f, 0.f, 0.f);
        for (int j = 0; j < NRES; j++) {
            float4 vv = *(const float4*)&g_v[j * 192 + ch4];
            float av = a_sh[h * NRES + j];
            acc.x += av * vv.x; acc.y += av * vv.y;
            acc.z += av * vv.z; acc.w += av * vv.w;
        }
        *(float4*)&g_cat[i * 2112 + ch4] = acc;
    } else if (tid < 376) {
        // o_pt (global frame): 72 threads x 4 channels = 288
        int ch4 = (tid - 304) * 4;
        int h = ch4 / 24;
        float4 acc = make_float4(0.f, 0.f, 0.f, 0.f);
        for (int j = 0; j < NRES; j++) {
            float4 pv = *(const float4*)&g_vpts[j * 288 + ch4];
            float av = a_sh[h * NRES + j];
            acc.x += av * pv.x; acc.y += av * pv.y;
            acc.z += av * pv.z; acc.w += av * pv.w;
        }
        *(float4*)&g_opt[i * 288 + ch4] = acc;
    }
    __syncthreads();
    for (int idx = tid; idx < NH * CZ; idx += 384)
        g_cat[i * 2112 + 576 + idx] = op_acc[idx];
}

// ---------------- kernel D3: inverse frame + norms ----------------
__global__ void k_rot_back(const float* __restrict__ rot, const float* __restrict__ trans) {
    int i = blockIdx.x;
    int r = threadIdx.x;  // 0..95 = h*8+p
    float g0 = g_opt[i * 288 + r * 3 + 0] - trans[i * 3 + 0];
    float g1 = g_opt[i * 288 + r * 3 + 1] - trans[i * 3 + 1];
    float g2 = g_opt[i * 288 + r * 3 + 2] - trans[i * 3 + 2];
    float lx = rot[i * 9 + 0] * g0 + rot[i * 9 + 3] * g1 + rot[i * 9 + 6] * g2;
    float ly = rot[i * 9 + 1] * g0 + rot[i * 9 + 4] * g1 + rot[i * 9 + 7] * g2;
    float lz = rot[i * 9 + 2] * g0 + rot[i * 9 + 5] * g1 + rot[i * 9 + 8] * g2;
    float nrm = sqrtf(lx * lx + ly * ly + lz * lz + 1e-8f);
    g_cat[i * 2112 + 192 + r] = lx;
    g_cat[i * 2112 + 288 + r] = ly;
    g_cat[i * 2112 + 384 + r] = lz;
    g_cat[i * 2112 + 480 + r] = nrm;
}

// ---------------- kernel E: out = cat @ Wout + bout ----------------
__global__ void k_out(const float* __restrict__ Wout, const float* __restrict__ bout,
                      float* __restrict__ out) {
    // grid (128, 3), block 128: 4 rows x 128 cols per block
    int i0 = blockIdx.x * 4;
    int oc0 = blockIdx.y * 128;
    __shared__ float cat_sh[4][2112];  // ~33 KB
    int tid = threadIdx.x;
    for (int idx = tid; idx < 4 * 2112; idx += 128) {
        int r = idx / 2112, k = idx % 2112;
        cat_sh[r][k] = g_cat[(i0 + r) * 2112 + k];
    }
    __syncthreads();
    int rg = tid >> 5, cg = tid & 31;
    int col = oc0 + cg * 4;
    float4 acc = *(const float4*)&bout[col];
    const float* ws = &Wout[col];
    #pragma unroll 4
    for (int k = 0; k < 2112; k++) {
        float4 w = *(const float4*)&ws[k * 384];
        float a = cat_sh[rg][k];
        acc.x += a * w.x; acc.y += a * w.y;
        acc.z += a * w.z; acc.w += a * w.w;
    }
    *(float4*)&out[(i0 + rg) * 384 + col] = acc;
}

extern "C" void kernel_launch(void* const* d_in, const int* in_sizes, int n_in,
                              void* d_out, int out_size) {
    const float* s     = (const float*)d_in[0];
    const float* z     = (const float*)d_in[1];
    const float* rot   = (const float*)d_in[2];
    const float* trans = (const float*)d_in[3];
    const float* mask  = (const float*)d_in[4];
    const float* Wq    = (const float*)d_in[5];
    const float* bq    = (const float*)d_in[6];
    const float* Wkv   = (const float*)d_in[7];
    const float* bkv   = (const float*)d_in[8];
    const float* Wqp   = (const float*)d_in[9];
    const float* bqp   = (const float*)d_in[10];
    const float* Wkvp  = (const float*)d_in[11];
    const float* bkvp  = (const float*)d_in[12];
    const float* Wb    = (const float*)d_in[13];
    const float* bb    = (const float*)d_in[14];
    const float* hwts  = (const float*)d_in[15];
    const float* Wout  = (const float*)d_in[16];
    const float* bout  = (const float*)d_in[17];
    float* out = (float*)d_out;

    k_proj<<<NRES, 256>>>(s, rot, trans, Wq, bq, Wkv, bkv, Wqp, bqp, Wkvp, bkvp, hwts);
    k_bias<<<2048, 256>>>(z, Wb);
    k_logits<<<dim3(NRES, NH), 256>>>(bb, mask);
    k_softmax<<<NH * NRES, 256>>>();
    k_att_apply<<<NRES, 384>>>(z);
    k_rot_back<<<NRES, 96>>>(rot, trans);
    k_out<<<dim3(128, 3), 128>>>(Wout, bout, out);
}

// round 5
// speedup vs baseline: 2.8503x; 2.7861x over previous
#include <cuda_runtime.h>
#include <math.h>

#define NRES 512
#define CS 384
#define CZ 128
#define CH 16
#define NH 12
#define PQ 4
#define PV 8

// ---------------- device scratch ----------------
__device__ __align__(16) float g_proj[NRES * 1152];           // q|kv|qp|kvp
__device__ __align__(16) float g_q[NRES * NH * CH];           // [i][h][c]
__device__ __align__(16) float g_kT[NH * NRES * CH];          // [h][j][c]
__device__ __align__(16) float g_v2[NRES * NH * 40];          // [j][h][v(16)|vpts(24)]
__device__ __align__(16) float g_qpts[NRES * NH * 12];        // [i][h*12+p*3+d]
__device__ __align__(16) float g_kptsT[NH * NRES * 12];       // [h][j*12+p*3+d]
__device__ __align__(16) float g_a[NH * NRES * NRES];         // [h][i][j]
__device__ __align__(16) float g_opt[NRES * NH * PV * 3];     // [i][h*24+p*3+d]
__device__ __align__(16) float g_cat[NRES * 2112];
__device__ __align__(16) float g_opart[4 * NRES * 384];
__device__ float g_hw[NH];

// =============== K1: tiled GEMM, out[512x1152] = s @ [Wq|Wkv|Wqp|Wkvp] ===============
__global__ void k_gemm_proj(const float* __restrict__ s,
                            const float* __restrict__ Wq, const float* __restrict__ bq,
                            const float* __restrict__ Wkv, const float* __restrict__ bkv,
                            const float* __restrict__ Wqp, const float* __restrict__ bqp,
                            const float* __restrict__ Wkvp, const float* __restrict__ bkvp) {
    __shared__ float s_sh[64 * 36];
    __shared__ float w_sh[32 * 48];
    int tid = threadIdx.x;            // 192
    int tx = tid % 12, ty = tid / 12; // tx: 12 col-groups of 4, ty: 16 row-groups of 4
    int r0 = blockIdx.x * 64;
    int by = blockIdx.y;

    const float* W; const float* bv; int outw, coff, gc0;
    if (by < 4)       { W = Wq;   bv = bq;   outw = 192; coff = 48 * by;        gc0 = coff; }
    else if (by < 12) { W = Wkv;  bv = bkv;  outw = 384; coff = 48 * (by - 4);  gc0 = 192 + coff; }
    else if (by < 15) { W = Wqp;  bv = bqp;  outw = 144; coff = 48 * (by - 12); gc0 = 576 + coff; }
    else              { W = Wkvp; bv = bkvp; outw = 432; coff = 48 * (by - 15); gc0 = 720 + coff; }

    float acc[4][4];
    #pragma unroll
    for (int r = 0; r < 4; r++)
        #pragma unroll
        for (int u = 0; u < 4; u++) acc[r][u] = 0.f;

    for (int kt = 0; kt < 12; kt++) {
        int k0 = kt * 32;
        for (int idx = tid; idx < 512; idx += 192) {
            int r = idx >> 3, c4 = (idx & 7) << 2;
            *(float4*)&s_sh[r * 36 + c4] = *(const float4*)&s[(r0 + r) * 384 + k0 + c4];
        }
        for (int idx = tid; idx < 384; idx += 192) {
            int k = idx / 12, c4 = (idx % 12) << 2;
            *(float4*)&w_sh[k * 48 + c4] = *(const float4*)&W[(k0 + k) * outw + coff + c4];
        }
        __syncthreads();
        #pragma unroll 8
        for (int k = 0; k < 32; k++) {
            float a0 = s_sh[(ty * 4 + 0) * 36 + k];
            float a1 = s_sh[(ty * 4 + 1) * 36 + k];
            float a2 = s_sh[(ty * 4 + 2) * 36 + k];
            float a3 = s_sh[(ty * 4 + 3) * 36 + k];
            float4 b = *(const float4*)&w_sh[k * 48 + tx * 4];
            acc[0][0] += a0 * b.x; acc[0][1] += a0 * b.y; acc[0][2] += a0 * b.z; acc[0][3] += a0 * b.w;
            acc[1][0] += a1 * b.x; acc[1][1] += a1 * b.y; acc[1][2] += a1 * b.z; acc[1][3] += a1 * b.w;
            acc[2][0] += a2 * b.x; acc[2][1] += a2 * b.y; acc[2][2] += a2 * b.z; acc[2][3] += a2 * b.w;
            acc[3][0] += a3 * b.x; acc[3][1] += a3 * b.y; acc[3][2] += a3 * b.z; acc[3][3] += a3 * b.w;
        }
        __syncthreads();
    }
    float4 bbv = *(const float4*)&bv[coff + tx * 4];
    #pragma unroll
    for (int r = 0; r < 4; r++) {
        float4 o;
        o.x = acc[r][0] + bbv.x; o.y = acc[r][1] + bbv.y;
        o.z = acc[r][2] + bbv.z; o.w = acc[r][3] + bbv.w;
        *(float4*)&g_proj[(r0 + ty * 4 + r) * 1152 + gc0 + tx * 4] = o;
    }
}

// =============== K2: scatter + frame transform ===============
__global__ void k_scatter(const float* __restrict__ rot, const float* __restrict__ trans,
                          const float* __restrict__ hwts) {
    int i = blockIdx.x;
    int tid = threadIdx.x;  // 192
    const float* pr = &g_proj[i * 1152];
    if (i == 0 && tid < NH) {
        float x = hwts[tid];
        float sp = (x > 20.f) ? x : log1pf(expf(x));
        g_hw[tid] = sp * 0.13608276348795434f;  // softplus * sqrt(1/54)
    }
    for (int c = tid; c < 576; c += 192) {
        float val = pr[c];
        if (c < 192) g_q[i * 192 + c] = val;
        else {
            int cc = c - 192; int h = cc >> 5, r = cc & 31;
            if (r < 16) g_kT[h * (NRES * CH) + i * CH + r] = val;
            else        g_v2[i * 480 + h * 40 + (r - 16)] = val;
        }
    }
    // points
    float R[9], T[3];
    #pragma unroll
    for (int d = 0; d < 9; d++) R[d] = rot[i * 9 + d];
    #pragma unroll
    for (int d = 0; d < 3; d++) T[d] = trans[i * 3 + d];
    if (tid < 48) {  // q points: h 0..11, p 0..3
        float pl[3];
        #pragma unroll
        for (int d = 0; d < 3; d++) pl[d] = pr[576 + d * 48 + tid];
        #pragma unroll
        for (int d = 0; d < 3; d++) {
            float g = R[d * 3 + 0] * pl[0] + R[d * 3 + 1] * pl[1] + R[d * 3 + 2] * pl[2] + T[d];
            g_qpts[i * 144 + tid * 3 + d] = g;  // tid = h*4+p -> h*12+p*3
        }
    } else {         // kv points: idx = h*12+pp
        int idx = tid - 48; int h = idx / 12, pp = idx % 12;
        float pl[3];
        #pragma unroll
        for (int d = 0; d < 3; d++) pl[d] = pr[720 + d * 144 + idx];
        #pragma unroll
        for (int d = 0; d < 3; d++) {
            float g = R[d * 3 + 0] * pl[0] + R[d * 3 + 1] * pl[1] + R[d * 3 + 2] * pl[2] + T[d];
            if (pp < 4) g_kptsT[h * (NRES * 12) + i * 12 + pp * 3 + d] = g;
            else        g_v2[i * 480 + h * 40 + 16 + (pp - 4) * 3 + d] = g;
        }
    }
}

// =============== K3: fused bias + logits + softmax, per residue i ===============
// dyn smem: zc[128*132] wbT[12*128] bias[12*512] qs[192] qps[144] red[32]
__global__ void k_fused(const float* __restrict__ z, const float* __restrict__ Wb,
                        const float* __restrict__ bb, const float* __restrict__ mask) {
    extern __shared__ float sm[];
    float* zc   = sm;            // 16896
    float* wbT  = sm + 16896;    // 1536
    float* bias = sm + 18432;    // 6144
    float* qs   = sm + 24576;    // 192
    float* qps  = sm + 24768;    // 144
    float* red  = sm + 24912;    // 32
    int i = blockIdx.x;
    int tid = threadIdx.x;       // 512
    int lane = tid & 31, wid = tid >> 5;

    // one-time loads
    for (int idx = tid; idx < 1536; idx += 512) {
        int h = idx >> 7, k = idx & 127;
        wbT[idx] = Wb[k * 12 + h];
    }
    if (tid < 192) qs[tid] = g_q[i * 192 + tid];
    if (tid < 144) qps[tid] = g_qpts[i * 144 + tid];

    // ---- phase A: bias[h][j] = z[i,j,:] . Wb[:,h] ----
    for (int jc = 0; jc < NRES; jc += 128) {
        __syncthreads();
        for (int job = tid; job < 4096; job += 512) {
            int row = job >> 5, c4 = (job & 31) << 2;
            *(float4*)&zc[row * 132 + c4] =
                *(const float4*)&z[((size_t)(i * NRES + jc + row)) * CZ + c4];
        }
        __syncthreads();
        #pragma unroll
        for (int p = 0; p < 3; p++) {
            int task = tid + p * 512;      // < 1536
            int h = task >> 7, j = task & 127;
            float acc = 0.f;
            #pragma unroll 8
            for (int k4 = 0; k4 < 32; k4++) {
                float4 zv = *(const float4*)&zc[j * 132 + k4 * 4];
                float4 wv = *(const float4*)&wbT[h * 128 + k4 * 4];
                acc += zv.x * wv.x + zv.y * wv.y + zv.z * wv.z + zv.w * wv.w;
            }
            bias[h * NRES + jc + j] = acc;
        }
    }
    __syncthreads();

    // ---- phase B: logits for all h (thread <-> j) ----
    int j = tid;
    float mi = mask[i];
    float mj = mask[j];
    float mterm = 100000.0f * (mi * mj - 1.0f);
    const float C1 = 0.14433756729740643f;  // sqrt(1/48)
    const float C2 = 0.5773502691896258f;   // sqrt(1/3)
    #pragma unroll
    for (int h = 0; h < 12; h++) {
        float qk = 0.f;
        const float* kr = &g_kT[h * (NRES * CH) + j * CH];
        #pragma unroll
        for (int c4 = 0; c4 < 4; c4++) {
            float4 kv = *(const float4*)&kr[c4 * 4];
            qk += qs[h * 16 + c4 * 4 + 0] * kv.x + qs[h * 16 + c4 * 4 + 1] * kv.y +
                  qs[h * 16 + c4 * 4 + 2] * kv.z + qs[h * 16 + c4 * 4 + 3] * kv.w;
        }
        float d2 = 0.f;
        const float* kp = &g_kptsT[h * (NRES * 12) + j * 12];
        #pragma unroll
        for (int t4 = 0; t4 < 3; t4++) {
            float4 pv = *(const float4*)&kp[t4 * 4];
            float d0 = qps[h * 12 + t4 * 4 + 0] - pv.x;
            float d1 = qps[h * 12 + t4 * 4 + 1] - pv.y;
            float d2a = qps[h * 12 + t4 * 4 + 2] - pv.z;
            float d3 = qps[h * 12 + t4 * 4 + 3] - pv.w;
            d2 += d0 * d0 + d1 * d1 + d2a * d2a + d3 * d3;
        }
        float lg = C1 * qk + C2 * (bias[h * NRES + j] + bb[h]) - 0.5f * g_hw[h] * d2 + mterm;
        bias[h * NRES + j] = lg;  // own slot: safe overwrite
    }
    __syncthreads();

    // ---- phase C: softmax per head ----
    for (int h = 0; h < 12; h++) {
        float v = bias[h * NRES + tid];
        float m = v;
        #pragma unroll
        for (int off = 16; off > 0; off >>= 1) m = fmaxf(m, __shfl_xor_sync(0xffffffffu, m, off));
        if (lane == 0) red[wid] = m;
        __syncthreads();
        if (tid < 16) {
            float mm = red[tid];
            #pragma unroll
            for (int off = 8; off > 0; off >>= 1) mm = fmaxf(mm, __shfl_xor_sync(0x0000ffffu, mm, off));
            if (tid == 0) red[0] = mm;
        }
        __syncthreads();
        float e = __expf(v - red[0]);
        float s = e;
        #pragma unroll
        for (int off = 16; off > 0; off >>= 1) s += __shfl_xor_sync(0xffffffffu, s, off);
        if (lane == 0) red[16 + wid] = s;
        __syncthreads();
        if (tid < 16) {
            float ss = red[16 + tid];
            #pragma unroll
            for (int off = 8; off > 0; off >>= 1) ss += __shfl_xor_sync(0x0000ffffu, ss, off);
            if (tid == 0) red[16] = ss;
        }
        __syncthreads();
        g_a[((size_t)h * NRES + i) * NRES + tid] = e * (1.0f / red[16]);
        __syncthreads();
    }
}

// =============== K4: o + o_pt GEMM per (h, i-tile of 32) ===============
__global__ void k_ov() {
    __shared__ float a_t[32 * 132];   // 16.9 KB
    __shared__ float v2_t[128 * 40];  // 20.5 KB
    int h = blockIdx.x;
    int i0 = blockIdx.y * 32;
    int tid = threadIdx.x;  // 128
    int ti = tid & 15;      // rows ti and ti+16
    int tc = tid >> 4;      // 0..7 -> ch = tc*5..tc*5+4
    float acc0[5], acc1[5];
    #pragma unroll
    for (int u = 0; u < 5; u++) { acc0[u] = 0.f; acc1[u] = 0.f; }

    for (int jc = 0; jc < NRES; jc += 128) {
        __syncthreads();
        for (int job = tid; job < 1024; job += 128) {
            int il = job >> 5, j4 = (job & 31) << 2;
            *(float4*)&a_t[il * 132 + j4] =
                *(const float4*)&g_a[((size_t)h * NRES + i0 + il) * NRES + jc + j4];
        }
        for (int job = tid; job < 1280; job += 128) {
            int jj = job / 10, c4 = (job % 10) << 2;
            *(float4*)&v2_t[jj * 40 + c4] = *(const float4*)&g_v2[(jc + jj) * 480 + h * 40 + c4];
        }
        __syncthreads();
        #pragma unroll 4
        for (int jj = 0; jj < 128; jj++) {
            float a0 = a_t[ti * 132 + jj];
            float a1 = a_t[(ti + 16) * 132 + jj];
            #pragma unroll
            for (int u = 0; u < 5; u++) {
                float vv = v2_t[jj * 40 + tc * 5 + u];
                acc0[u] += a0 * vv;
                acc1[u] += a1 * vv;
            }
        }
    }
    #pragma unroll
    for (int u = 0; u < 5; u++) {
        int ch = tc * 5 + u;
        int ia = i0 + ti, ib = i0 + ti + 16;
        if (ch < 16) {
            g_cat[ia * 2112 + h * 16 + ch] = acc0[u];
            g_cat[ib * 2112 + h * 16 + ch] = acc1[u];
        } else {
            g_opt[ia * 288 + h * 24 + (ch - 16)] = acc0[u];
            g_opt[ib * 288 + h * 24 + (ch - 16)] = acc1[u];
        }
    }
}

// =============== K5: o_pair per residue i (streams z once) ===============
// dyn smem: a_sh[12*512] zc[128*132]
__global__ void k_opair(const float* __restrict__ z) {
    extern __shared__ float sm[];
    float* a_sh = sm;          // 6144
    float* zc = sm + 6144;     // 16896
    int i = blockIdx.x;
    int tid = threadIdx.x;     // 384
    for (int idx = tid; idx < 6144; idx += 384) {
        int h = idx >> 9, j = idx & 511;
        a_sh[idx] = g_a[((size_t)h * NRES + i) * NRES + j];
    }
    int hp = tid >> 5;         // 0..5 (compute threads tid<192)
    int cg = tid & 31;
    float4 acc0 = make_float4(0.f, 0.f, 0.f, 0.f);
    float4 acc1 = make_float4(0.f, 0.f, 0.f, 0.f);

    for (int jc = 0; jc < NRES; jc += 128) {
        __syncthreads();
        for (int job = tid; job < 4096; job += 384) {
            int row = job >> 5, c4 = (job & 31) << 2;
            *(float4*)&zc[row * 132 + c4] =
                *(const float4*)&z[((size_t)(i * NRES + jc + row)) * CZ + c4];
        }
        __syncthreads();
        if (tid < 192) {
            #pragma unroll 4
            for (int jj = 0; jj < 128; jj++) {
                float4 zv = *(const float4*)&zc[jj * 132 + cg * 4];
                float a0 = a_sh[hp * NRES + jc + jj];
                float a1 = a_sh[(hp + 6) * NRES + jc + jj];
                acc0.x += a0 * zv.x; acc0.y += a0 * zv.y; acc0.z += a0 * zv.z; acc0.w += a0 * zv.w;
                acc1.x += a1 * zv.x; acc1.y += a1 * zv.y; acc1.z += a1 * zv.z; acc1.w += a1 * zv.w;
            }
        }
    }
    if (tid < 192) {
        *(float4*)&g_cat[i * 2112 + 576 + hp * 128 + cg * 4] = acc0;
        *(float4*)&g_cat[i * 2112 + 576 + (hp + 6) * 128 + cg * 4] = acc1;
    }
}

// =============== K6: inverse frame + norms ===============
__global__ void k_rot_back(const float* __restrict__ rot, const float* __restrict__ trans) {
    int i = blockIdx.x;
    int r = threadIdx.x;  // 0..95 = h*8+p
    float g0 = g_opt[i * 288 + r * 3 + 0] - trans[i * 3 + 0];
    float g1 = g_opt[i * 288 + r * 3 + 1] - trans[i * 3 + 1];
    float g2 = g_opt[i * 288 + r * 3 + 2] - trans[i * 3 + 2];
    float lx = rot[i * 9 + 0] * g0 + rot[i * 9 + 3] * g1 + rot[i * 9 + 6] * g2;
    float ly = rot[i * 9 + 1] * g0 + rot[i * 9 + 4] * g1 + rot[i * 9 + 7] * g2;
    float lz = rot[i * 9 + 2] * g0 + rot[i * 9 + 5] * g1 + rot[i * 9 + 8] * g2;
    float nrm = sqrtf(lx * lx + ly * ly + lz * lz + 1e-8f);
    g_cat[i * 2112 + 192 + r] = lx;
    g_cat[i * 2112 + 288 + r] = ly;
    g_cat[i * 2112 + 384 + r] = lz;
    g_cat[i * 2112 + 480 + r] = nrm;
}

// =============== K7: split-K output GEMM ===============
// grid (16 i-tiles of 32, 8 col-tiles of 48, 4 k-splits of 528), block 192
__global__ void k_out(const float* __restrict__ Wout) {
    __shared__ float cat_s[32 * 48];
    __shared__ float w_s[48 * 48];
    int tid = threadIdx.x;
    int tx = tid % 12, ty = tid / 12;  // tx: cols(4), ty: rows ty & ty+16
    int i0 = blockIdx.x * 32;
    int c0 = blockIdx.y * 48;
    int ks = blockIdx.z;
    float4 acc0 = make_float4(0.f, 0.f, 0.f, 0.f);
    float4 acc1 = make_float4(0.f, 0.f, 0.f, 0.f);

    for (int kc = 0; kc < 11; kc++) {
        int k0 = ks * 528 + kc * 48;
        for (int job = tid; job < 384; job += 192) {
            int r = job / 12, c4 = (job % 12) << 2;
            *(float4*)&cat_s[r * 48 + c4] = *(const float4*)&g_cat[(i0 + r) * 2112 + k0 + c4];
        }
        for (int job = tid; job < 576; job += 192) {
            int r = job / 12, c4 = (job % 12) << 2;
            *(float4*)&w_s[r * 48 + c4] = *(const float4*)&Wout[(k0 + r) * 384 + c0 + c4];
        }
        __syncthreads();
        #pragma unroll 8
        for (int k = 0; k < 48; k++) {
            float a0 = cat_s[ty * 48 + k];
            float a1 = cat_s[(ty + 16) * 48 + k];
            float4 wv = *(const float4*)&w_s[k * 48 + tx * 4];
            acc0.x += a0 * wv.x; acc0.y += a0 * wv.y; acc0.z += a0 * wv.z; acc0.w += a0 * wv.w;
            acc1.x += a1 * wv.x; acc1.y += a1 * wv.y; acc1.z += a1 * wv.z; acc1.w += a1 * wv.w;
        }
        __syncthreads();
    }
    *(float4*)&g_opart[((size_t)ks * NRES + i0 + ty) * 384 + c0 + tx * 4] = acc0;
    *(float4*)&g_opart[((size_t)ks * NRES + i0 + ty + 16) * 384 + c0 + tx * 4] = acc1;
}

__global__ void k_out_red(const float* __restrict__ bout, float* __restrict__ out) {
    int f = blockIdx.x * 256 + threadIdx.x;  // 49152 float4 jobs
    int i = f / 96;
    int c4 = (f % 96) * 4;
    float4 s0 = *(const float4*)&g_opart[(size_t)0 * 196608 + i * 384 + c4];
    float4 s1 = *(const float4*)&g_opart[(size_t)1 * 196608 + i * 384 + c4];
    float4 s2 = *(const float4*)&g_opart[(size_t)2 * 196608 + i * 384 + c4];
    float4 s3 = *(const float4*)&g_opart[(size_t)3 * 196608 + i * 384 + c4];
    float4 bv = *(const float4*)&bout[c4];
    float4 o;
    o.x = s0.x + s1.x + s2.x + s3.x + bv.x;
    o.y = s0.y + s1.y + s2.y + s3.y + bv.y;
    o.z = s0.z + s1.z + s2.z + s3.z + bv.z;
    o.w = s0.w + s1.w + s2.w + s3.w + bv.w;
    *(float4*)&out[i * 384 + c4] = o;
}

extern "C" void kernel_launch(void* const* d_in, const int* in_sizes, int n_in,
                              void* d_out, int out_size) {
    const float* s     = (const float*)d_in[0];
    const float* z     = (const float*)d_in[1];
    const float* rot   = (const float*)d_in[2];
    const float* trans = (const float*)d_in[3];
    const float* mask  = (const float*)d_in[4];
    const float* Wq    = (const float*)d_in[5];
    const float* bq    = (const float*)d_in[6];
    const float* Wkv   = (const float*)d_in[7];
    const float* bkv   = (const float*)d_in[8];
    const float* Wqp   = (const float*)d_in[9];
    const float* bqp   = (const float*)d_in[10];
    const float* Wkvp  = (const float*)d_in[11];
    const float* bkvp  = (const float*)d_in[12];
    const float* Wb    = (const float*)d_in[13];
    const float* bb    = (const float*)d_in[14];
    const float* hwts  = (const float*)d_in[15];
    const float* Wout  = (const float*)d_in[16];
    const float* bout  = (const float*)d_in[17];
    float* out = (float*)d_out;

    const int FUSED_SMEM = 24944 * 4;   // 99776 B
    const int OPAIR_SMEM = 23040 * 4;   // 92160 B
    cudaFuncSetAttribute(k_fused, cudaFuncAttributeMaxDynamicSharedMemorySize, FUSED_SMEM);
    cudaFuncSetAttribute(k_opair, cudaFuncAttributeMaxDynamicSharedMemorySize, OPAIR_SMEM);

    k_gemm_proj<<<dim3(8, 24), 192>>>(s, Wq, bq, Wkv, bkv, Wqp, bqp, Wkvp, bkvp);
    k_scatter<<<NRES, 192>>>(rot, trans, hwts);
    k_fused<<<NRES, 512, FUSED_SMEM>>>(z, Wb, bb, mask);
    k_ov<<<dim3(12, 16), 128>>>();
    k_opair<<<NRES, 384, OPAIR_SMEM>>>(z);
    k_rot_back<<<NRES, 96>>>(rot, trans);
    k_out<<<dim3(16, 8, 4), 192>>>(Wout);
    k_out_red<<<192, 256>>>(bout, out);
}

// round 6
// speedup vs baseline: 3.9390x; 1.3820x over previous
#include <cuda_runtime.h>
#include <math.h>

#define NRES 512
#define CS 384
#define CZ 128
#define CH 16
#define NH 12
#define PQ 4
#define PV 8

// ---------------- device scratch ----------------
__device__ __align__(16) float g_proj[NRES * 1152];           // q|kv|qp|kvp
__device__ __align__(16) float g_v2[NRES * NH * 40];          // [j][h][v(16)|vpts(24)]
__device__ __align__(16) float g_A[NH * NRES * 32];           // logit lhs
__device__ __align__(16) float g_B[NH * NRES * 32];           // logit rhs
__device__ __align__(16) float g_pre[(size_t)NH * NRES * NRES]; // [h][i][j] pre-logits
__device__ __align__(16) float g_a[(size_t)NH * NRES * NRES];   // [h][i][j] softmaxed
__device__ __align__(16) float g_ovp[2 * NRES * 480];         // j-split partials
__device__ __align__(16) float g_cat[NRES * 2112];
__device__ __align__(16) float g_opart[4 * NRES * 384];

// =============== K1: tiled GEMM, g_proj[512x1152] = s @ [Wq|Wkv|Wqp|Wkvp] ===============
__global__ void k_gemm_proj(const float* __restrict__ s,
                            const float* __restrict__ Wq, const float* __restrict__ bq,
                            const float* __restrict__ Wkv, const float* __restrict__ bkv,
                            const float* __restrict__ Wqp, const float* __restrict__ bqp,
                            const float* __restrict__ Wkvp, const float* __restrict__ bkvp) {
    __shared__ float s_sh[64 * 36];
    __shared__ float w_sh[32 * 48];
    int tid = threadIdx.x;            // 192
    int tx = tid % 12, ty = tid / 12;
    int r0 = blockIdx.x * 64;
    int by = blockIdx.y;

    const float* W; const float* bv; int outw, coff, gc0;
    if (by < 4)       { W = Wq;   bv = bq;   outw = 192; coff = 48 * by;        gc0 = coff; }
    else if (by < 12) { W = Wkv;  bv = bkv;  outw = 384; coff = 48 * (by - 4);  gc0 = 192 + coff; }
    else if (by < 15) { W = Wqp;  bv = bqp;  outw = 144; coff = 48 * (by - 12); gc0 = 576 + coff; }
    else              { W = Wkvp; bv = bkvp; outw = 432; coff = 48 * (by - 15); gc0 = 720 + coff; }

    float acc[4][4];
    #pragma unroll
    for (int r = 0; r < 4; r++)
        #pragma unroll
        for (int u = 0; u < 4; u++) acc[r][u] = 0.f;

    for (int kt = 0; kt < 12; kt++) {
        int k0 = kt * 32;
        for (int idx = tid; idx < 512; idx += 192) {
            int r = idx >> 3, c4 = (idx & 7) << 2;
            *(float4*)&s_sh[r * 36 + c4] = *(const float4*)&s[(r0 + r) * 384 + k0 + c4];
        }
        for (int idx = tid; idx < 384; idx += 192) {
            int k = idx / 12, c4 = (idx % 12) << 2;
            *(float4*)&w_sh[k * 48 + c4] = *(const float4*)&W[(k0 + k) * outw + coff + c4];
        }
        __syncthreads();
        #pragma unroll 8
        for (int k = 0; k < 32; k++) {
            float a0 = s_sh[(ty * 4 + 0) * 36 + k];
            float a1 = s_sh[(ty * 4 + 1) * 36 + k];
            float a2 = s_sh[(ty * 4 + 2) * 36 + k];
            float a3 = s_sh[(ty * 4 + 3) * 36 + k];
            float4 b = *(const float4*)&w_sh[k * 48 + tx * 4];
            acc[0][0] += a0 * b.x; acc[0][1] += a0 * b.y; acc[0][2] += a0 * b.z; acc[0][3] += a0 * b.w;
            acc[1][0] += a1 * b.x; acc[1][1] += a1 * b.y; acc[1][2] += a1 * b.z; acc[1][3] += a1 * b.w;
            acc[2][0] += a2 * b.x; acc[2][1] += a2 * b.y; acc[2][2] += a2 * b.z; acc[2][3] += a2 * b.w;
            acc[3][0] += a3 * b.x; acc[3][1] += a3 * b.y; acc[3][2] += a3 * b.z; acc[3][3] += a3 * b.w;
        }
        __syncthreads();
    }
    float4 bbv = *(const float4*)&bv[coff + tx * 4];
    #pragma unroll
    for (int r = 0; r < 4; r++) {
        float4 o;
        o.x = acc[r][0] + bbv.x; o.y = acc[r][1] + bbv.y;
        o.z = acc[r][2] + bbv.z; o.w = acc[r][3] + bbv.w;
        *(float4*)&g_proj[(r0 + ty * 4 + r) * 1152 + gc0 + tx * 4] = o;
    }
}

// =============== K2: scatter + frame transform + build A/B logit factors ===============
__global__ void k_scatter(const float* __restrict__ rot, const float* __restrict__ trans,
                          const float* __restrict__ hwts, const float* __restrict__ mask) {
    int i = blockIdx.x;
    int tid = threadIdx.x;  // 192
    __shared__ float sp_q[144];  // h*12 + p*3 + d
    __shared__ float sp_k[144];
    __shared__ float s_hw[12], s_q2[12], s_k2[12];
    const float* pr = &g_proj[i * 1152];

    if (tid < 12) {
        float x = hwts[tid];
        float sp = (x > 20.f) ? x : log1pf(expf(x));
        s_hw[tid] = sp * 0.13608276348795434f;  // softplus * sqrt(1/54)
    }
    float R[9], T[3];
    #pragma unroll
    for (int d = 0; d < 9; d++) R[d] = rot[i * 9 + d];
    #pragma unroll
    for (int d = 0; d < 3; d++) T[d] = trans[i * 3 + d];
    if (tid < 48) {  // q points: tid = h*4+p
        float pl[3];
        #pragma unroll
        for (int d = 0; d < 3; d++) pl[d] = pr[576 + d * 48 + tid];
        #pragma unroll
        for (int d = 0; d < 3; d++)
            sp_q[tid * 3 + d] = R[d * 3 + 0] * pl[0] + R[d * 3 + 1] * pl[1] + R[d * 3 + 2] * pl[2] + T[d];
    } else {         // kv points: idx = h*12+pp
        int idx = tid - 48; int h = idx / 12, pp = idx % 12;
        float pl[3];
        #pragma unroll
        for (int d = 0; d < 3; d++) pl[d] = pr[720 + d * 144 + idx];
        #pragma unroll
        for (int d = 0; d < 3; d++) {
            float g = R[d * 3 + 0] * pl[0] + R[d * 3 + 1] * pl[1] + R[d * 3 + 2] * pl[2] + T[d];
            if (pp < 4) sp_k[h * 12 + pp * 3 + d] = g;
            else        g_v2[i * 480 + h * 40 + 16 + (pp - 4) * 3 + d] = g;
        }
    }
    // v channels
    {
        int h = tid >> 4, c = tid & 15;
        g_v2[i * 480 + h * 40 + c] = pr[192 + h * 32 + 16 + c];
    }
    __syncthreads();
    if (tid < 12) {
        float sq = 0.f, sk = 0.f;
        #pragma unroll
        for (int t = 0; t < 12; t++) {
            float a = sp_q[tid * 12 + t]; sq += a * a;
            float b = sp_k[tid * 12 + t]; sk += b * b;
        }
        s_q2[tid] = sq; s_k2[tid] = sk;
    }
    __syncthreads();
    const float C1 = 0.14433756729740643f;  // sqrt(1/48)
    float mi = mask[i];
    {
        int h = tid >> 4, c = tid & 15;
        g_A[(h * NRES + i) * 32 + c] = C1 * pr[h * 16 + c];
        g_B[(h * NRES + i) * 32 + c] = pr[192 + h * 32 + c];
    }
    if (tid < 144) {
        int h = tid / 12, t = tid % 12;
        g_A[(h * NRES + i) * 32 + 16 + t] = s_hw[h] * sp_q[h * 12 + t];
        g_B[(h * NRES + i) * 32 + 16 + t] = sp_k[h * 12 + t];
    }
    if (tid < 12) {
        int h = tid; float hw = s_hw[h];
        float* A = &g_A[(h * NRES + i) * 32];
        float* B = &g_B[(h * NRES + i) * 32];
        A[28] = -0.5f * hw * s_q2[h];  B[28] = 1.f;
        A[29] = 1.f;                   B[29] = -0.5f * hw * s_k2[h];
        A[30] = 100000.0f * mi;        B[30] = mi;
        A[31] = 1.f;                   B[31] = -100000.0f;
    }
}

// =============== K3: pre-logit GEMM g_pre[h][i][j] = A[h,i,:32] . B[h,j,:32] ===============
__global__ void k_pre() {  // grid (8 it, 8 jt, 12 h), 256 threads
    __shared__ float a_t[64 * 33];
    __shared__ float b_t[64 * 33];
    int h = blockIdx.z;
    int i0 = blockIdx.x * 64, j0 = blockIdx.y * 64;
    int tid = threadIdx.x;
    for (int f = tid; f < 512; f += 256) {
        int r = f >> 3, k4 = (f & 7) << 2;
        float4 v = *(const float4*)&g_A[(h * NRES + i0 + r) * 32 + k4];
        a_t[r * 33 + k4] = v.x; a_t[r * 33 + k4 + 1] = v.y;
        a_t[r * 33 + k4 + 2] = v.z; a_t[r * 33 + k4 + 3] = v.w;
        float4 w = *(const float4*)&g_B[(h * NRES + j0 + r) * 32 + k4];
        b_t[r * 33 + k4] = w.x; b_t[r * 33 + k4 + 1] = w.y;
        b_t[r * 33 + k4 + 2] = w.z; b_t[r * 33 + k4 + 3] = w.w;
    }
    __syncthreads();
    int tx = tid & 15, ty = tid >> 4;
    float acc[4][4];
    #pragma unroll
    for (int r = 0; r < 4; r++)
        #pragma unroll
        for (int u = 0; u < 4; u++) acc[r][u] = 0.f;
    #pragma unroll 8
    for (int k = 0; k < 32; k++) {
        float av[4], bv[4];
        #pragma unroll
        for (int r = 0; r < 4; r++) av[r] = a_t[(ty * 4 + r) * 33 + k];
        #pragma unroll
        for (int u = 0; u < 4; u++) bv[u] = b_t[(tx * 4 + u) * 33 + k];
        #pragma unroll
        for (int r = 0; r < 4; r++)
            #pragma unroll
            for (int u = 0; u < 4; u++) acc[r][u] += av[r] * bv[u];
    }
    #pragma unroll
    for (int r = 0; r < 4; r++) {
        float4 o = make_float4(acc[r][0], acc[r][1], acc[r][2], acc[r][3]);
        *(float4*)&g_pre[((size_t)h * NRES + i0 + ty * 4 + r) * NRES + j0 + tx * 4] = o;
    }
}

// =============== K4: fused bias + logits + softmax + o_pair, per residue i ===============
// dyn smem: zc[128*132]=16896, av[12*512]=6144, wbT[12*128]=1536 -> 24576 floats = 98304 B
__global__ void k_fused(const float* __restrict__ z, const float* __restrict__ Wb,
                        const float* __restrict__ bb) {
    extern __shared__ float sm[];
    float* zc  = sm;
    float* av  = sm + 16896;
    float* wbT = sm + 23040;
    int i = blockIdx.x;
    int tid = threadIdx.x;  // 512
    for (int idx = tid; idx < 1536; idx += 512) {
        int h = idx >> 7, k = idx & 127;
        wbT[idx] = Wb[k * 12 + h];
    }
    int jl = tid & 127, hs = tid >> 7;

    // phase A: bias[h][j] = z[i,j,:] . Wb[:,h]
    for (int jc = 0; jc < 4; jc++) {
        __syncthreads();
        for (int f = tid; f < 4096; f += 512) {
            int r = f >> 5, c4 = (f & 31) << 2;
            *(float4*)&zc[r * 132 + c4] =
                *(const float4*)&z[((size_t)(i * NRES + jc * 128 + r)) * CZ + c4];
        }
        __syncthreads();
        float acc0 = 0.f, acc1 = 0.f, acc2 = 0.f;
        #pragma unroll 8
        for (int k4 = 0; k4 < 32; k4++) {
            float4 zv = *(const float4*)&zc[jl * 132 + k4 * 4];
            float4 w0 = *(const float4*)&wbT[(hs * 3 + 0) * 128 + k4 * 4];
            float4 w1 = *(const float4*)&wbT[(hs * 3 + 1) * 128 + k4 * 4];
            float4 w2 = *(const float4*)&wbT[(hs * 3 + 2) * 128 + k4 * 4];
            acc0 += zv.x * w0.x + zv.y * w0.y + zv.z * w0.z + zv.w * w0.w;
            acc1 += zv.x * w1.x + zv.y * w1.y + zv.z * w1.z + zv.w * w1.w;
            acc2 += zv.x * w2.x + zv.y * w2.y + zv.z * w2.z + zv.w * w2.w;
        }
        av[(hs * 3 + 0) * NRES + jc * 128 + jl] = acc0;
        av[(hs * 3 + 1) * NRES + jc * 128 + jl] = acc1;
        av[(hs * 3 + 2) * NRES + jc * 128 + jl] = acc2;
    }
    __syncthreads();

    // phase B: add pre-logits (coalesced)
    const float C2 = 0.5773502691896258f;  // sqrt(1/3)
    #pragma unroll
    for (int h = 0; h < 12; h++) {
        float lg = g_pre[((size_t)h * NRES + i) * NRES + tid] + C2 * (av[h * NRES + tid] + bb[h]);
        av[h * NRES + tid] = lg;
    }
    __syncthreads();

    // phase C: softmax, one warp per head
    int lane = tid & 31, wid = tid >> 5;
    if (wid < 12) {
        int h = wid;
        float vals[16];
        float m = -3.4e38f;
        #pragma unroll
        for (int u = 0; u < 16; u++) {
            vals[u] = av[h * NRES + u * 32 + lane];
            m = fmaxf(m, vals[u]);
        }
        #pragma unroll
        for (int off = 16; off > 0; off >>= 1) m = fmaxf(m, __shfl_xor_sync(0xffffffffu, m, off));
        float s = 0.f;
        #pragma unroll
        for (int u = 0; u < 16; u++) { vals[u] = __expf(vals[u] - m); s += vals[u]; }
        #pragma unroll
        for (int off = 16; off > 0; off >>= 1) s += __shfl_xor_sync(0xffffffffu, s, off);
        float inv = 1.0f / s;
        #pragma unroll
        for (int u = 0; u < 16; u++) {
            float an = vals[u] * inv;
            av[h * NRES + u * 32 + lane] = an;
            g_a[((size_t)h * NRES + i) * NRES + u * 32 + lane] = an;
        }
    }

    // phase D: o_pair = sum_j a[h][j] * z[i,j,:]  (z re-read, L2-resident)
    int cg = tid & 31, hh = tid >> 5;
    float4 acc = make_float4(0.f, 0.f, 0.f, 0.f);
    for (int jc = 0; jc < 4; jc++) {
        __syncthreads();
        for (int f = tid; f < 4096; f += 512) {
            int r = f >> 5, c4 = (f & 31) << 2;
            *(float4*)&zc[r * 132 + c4] =
                *(const float4*)&z[((size_t)(i * NRES + jc * 128 + r)) * CZ + c4];
        }
        __syncthreads();
        if (hh < 12) {
            #pragma unroll 4
            for (int jj = 0; jj < 128; jj++) {
                float a = av[hh * NRES + jc * 128 + jj];
                float4 zv = *(const float4*)&zc[jj * 132 + cg * 4];
                acc.x += a * zv.x; acc.y += a * zv.y;
                acc.z += a * zv.z; acc.w += a * zv.w;
            }
        }
    }
    if (hh < 12)
        *(float4*)&g_cat[i * 2112 + 576 + hh * 128 + cg * 4] = acc;
}

// =============== K5: o + o_pt GEMM, j-split partials ===============
// grid (16 i-tiles of 32, 12 h, 2 j-splits), 320 threads
__global__ void k_ov() {
    extern __shared__ float sm[];
    float* a_t  = sm;          // 32 * 260
    float* v2_t = sm + 8320;   // 256 * 40
    int i0 = blockIdx.x * 32;
    int h = blockIdx.y;
    int j0 = blockIdx.z * 256;
    int tid = threadIdx.x;
    for (int f = tid; f < 2048; f += 320) {
        int r = f >> 6, j4 = (f & 63) << 2;
        *(float4*)&a_t[r * 260 + j4] =
            *(const float4*)&g_a[((size_t)h * NRES + i0 + r) * NRES + j0 + j4];
    }
    for (int f = tid; f < 2560; f += 320) {
        int jj = f / 10, c4 = (f % 10) << 2;
        *(float4*)&v2_t[jj * 40 + c4] = *(const float4*)&g_v2[(j0 + jj) * 480 + h * 40 + c4];
    }
    __syncthreads();
    int row = tid & 31, cg = tid >> 5;  // cg 0..9
    float4 acc = make_float4(0.f, 0.f, 0.f, 0.f);
    #pragma unroll 4
    for (int j4 = 0; j4 < 64; j4++) {
        float4 a4 = *(const float4*)&a_t[row * 260 + j4 * 4];
        float4 v0 = *(const float4*)&v2_t[(j4 * 4 + 0) * 40 + cg * 4];
        float4 v1 = *(const float4*)&v2_t[(j4 * 4 + 1) * 40 + cg * 4];
        float4 v2 = *(const float4*)&v2_t[(j4 * 4 + 2) * 40 + cg * 4];
        float4 v3 = *(const float4*)&v2_t[(j4 * 4 + 3) * 40 + cg * 4];
        acc.x += a4.x * v0.x + a4.y * v1.x + a4.z * v2.x + a4.w * v3.x;
        acc.y += a4.x * v0.y + a4.y * v1.y + a4.z * v2.y + a4.w * v3.y;
        acc.z += a4.x * v0.z + a4.y * v1.z + a4.z * v2.z + a4.w * v3.z;
        acc.w += a4.x * v0.w + a4.y * v1.w + a4.z * v2.w + a4.w * v3.w;
    }
    *(float4*)&g_ovp[((size_t)blockIdx.z * NRES + i0 + row) * 480 + h * 40 + cg * 4] = acc;
}

// =============== K6: reduce j-split partials + inverse frame + norms ===============
__global__ void k_ovred(const float* __restrict__ rot, const float* __restrict__ trans) {
    int i = blockIdx.x;
    int tid = threadIdx.x;  // 192
    {
        int h = tid >> 4, c = tid & 15;
        float v = g_ovp[(size_t)i * 480 + h * 40 + c] +
                  g_ovp[(size_t)(NRES + i) * 480 + h * 40 + c];
        g_cat[i * 2112 + tid] = v;
    }
    if (tid < 96) {
        int h = tid >> 3, p = tid & 7;
        float s0 = g_ovp[(size_t)i * 480 + h * 40 + 16 + p * 3 + 0] +
                   g_ovp[(size_t)(NRES + i) * 480 + h * 40 + 16 + p * 3 + 0];
        float s1 = g_ovp[(size_t)i * 480 + h * 40 + 16 + p * 3 + 1] +
                   g_ovp[(size_t)(NRES + i) * 480 + h * 40 + 16 + p * 3 + 1];
        float s2 = g_ovp[(size_t)i * 480 + h * 40 + 16 + p * 3 + 2] +
                   g_ovp[(size_t)(NRES + i) * 480 + h * 40 + 16 + p * 3 + 2];
        float g0 = s0 - trans[i * 3 + 0];
        float g1 = s1 - trans[i * 3 + 1];
        float g2 = s2 - trans[i * 3 + 2];
        float lx = rot[i * 9 + 0] * g0 + rot[i * 9 + 3] * g1 + rot[i * 9 + 6] * g2;
        float ly = rot[i * 9 + 1] * g0 + rot[i * 9 + 4] * g1 + rot[i * 9 + 7] * g2;
        float lz = rot[i * 9 + 2] * g0 + rot[i * 9 + 5] * g1 + rot[i * 9 + 8] * g2;
        float nrm = sqrtf(lx * lx + ly * ly + lz * lz + 1e-8f);
        g_cat[i * 2112 + 192 + tid] = lx;
        g_cat[i * 2112 + 288 + tid] = ly;
        g_cat[i * 2112 + 384 + tid] = lz;
        g_cat[i * 2112 + 480 + tid] = nrm;
    }
}

// =============== K7: split-K output GEMM (64x48 tiles, 4x4 micro) ===============
__global__ void k_out(const float* __restrict__ Wout) {
    __shared__ float cat_s[64 * 48];
    __shared__ float w_s[48 * 48];
    int tid = threadIdx.x;             // 192
    int tx = tid % 12, ty = tid / 12;  // tx: 12 col4-groups, ty: 16 row4-groups
    int i0 = blockIdx.x * 64;
    int c0 = blockIdx.y * 48;
    int ks = blockIdx.z;
    float acc[4][4];
    #pragma unroll
    for (int r = 0; r < 4; r++)
        #pragma unroll
        for (int u = 0; u < 4; u++) acc[r][u] = 0.f;

    for (int kc = 0; kc < 11; kc++) {
        int k0 = ks * 528 + kc * 48;
        __syncthreads();
        for (int f = tid; f < 768; f += 192) {
            int r = f / 12, c4 = (f % 12) << 2;
            *(float4*)&cat_s[r * 48 + c4] = *(const float4*)&g_cat[(i0 + r) * 2112 + k0 + c4];
        }
        for (int f = tid; f < 576; f += 192) {
            int r = f / 12, c4 = (f % 12) << 2;
            *(float4*)&w_s[r * 48 + c4] = *(const float4*)&Wout[(k0 + r) * 384 + c0 + c4];
        }
        __syncthreads();
        #pragma unroll 8
        for (int k = 0; k < 48; k++) {
            float a0 = cat_s[(ty * 4 + 0) * 48 + k];
            float a1 = cat_s[(ty * 4 + 1) * 48 + k];
            float a2 = cat_s[(ty * 4 + 2) * 48 + k];
            float a3 = cat_s[(ty * 4 + 3) * 48 + k];
            float4 wv = *(const float4*)&w_s[k * 48 + tx * 4];
            acc[0][0] += a0 * wv.x; acc[0][1] += a0 * wv.y; acc[0][2] += a0 * wv.z; acc[0][3] += a0 * wv.w;
            acc[1][0] += a1 * wv.x; acc[1][1] += a1 * wv.y; acc[1][2] += a1 * wv.z; acc[1][3] += a1 * wv.w;
            acc[2][0] += a2 * wv.x; acc[2][1] += a2 * wv.y; acc[2][2] += a2 * wv.z; acc[2][3] += a2 * wv.w;
            acc[3][0] += a3 * wv.x; acc[3][1] += a3 * wv.y; acc[3][2] += a3 * wv.z; acc[3][3] += a3 * wv.w;
        }
    }
    #pragma unroll
    for (int r = 0; r < 4; r++) {
        float4 o = make_float4(acc[r][0], acc[r][1], acc[r][2], acc[r][3]);
        *(float4*)&g_opart[((size_t)ks * NRES + i0 + ty * 4 + r) * 384 + c0 + tx * 4] = o;
    }
}

__global__ void k_out_red(const float* __restrict__ bout, float* __restrict__ out) {
    int f = blockIdx.x * 256 + threadIdx.x;  // 49152 float4 jobs
    int i = f / 96;
    int c4 = (f % 96) * 4;
    float4 s0 = *(const float4*)&g_opart[(size_t)0 * 196608 + i * 384 + c4];
    float4 s1 = *(const float4*)&g_opart[(size_t)1 * 196608 + i * 384 + c4];
    float4 s2 = *(const float4*)&g_opart[(size_t)2 * 196608 + i * 384 + c4];
    float4 s3 = *(const float4*)&g_opart[(size_t)3 * 196608 + i * 384 + c4];
    float4 bv = *(const float4*)&bout[c4];
    float4 o;
    o.x = s0.x + s1.x + s2.x + s3.x + bv.x;
    o.y = s0.y + s1.y + s2.y + s3.y + bv.y;
    o.z = s0.z + s1.z + s2.z + s3.z + bv.z;
    o.w = s0.w + s1.w + s2.w + s3.w + bv.w;
    *(float4*)&out[i * 384 + c4] = o;
}

extern "C" void kernel_launch(void* const* d_in, const int* in_sizes, int n_in,
                              void* d_out, int out_size) {
    const float* s     = (const float*)d_in[0];
    const float* z     = (const float*)d_in[1];
    const float* rot   = (const float*)d_in[2];
    const float* trans = (const float*)d_in[3];
    const float* mask  = (const float*)d_in[4];
    const float* Wq    = (const float*)d_in[5];
    const float* bq    = (const float*)d_in[6];
    const float* Wkv   = (const float*)d_in[7];
    const float* bkv   = (const float*)d_in[8];
    const float* Wqp   = (const float*)d_in[9];
    const float* bqp   = (const float*)d_in[10];
    const float* Wkvp  = (const float*)d_in[11];
    const float* bkvp  = (const float*)d_in[12];
    const float* Wb    = (const float*)d_in[13];
    const float* bb    = (const float*)d_in[14];
    const float* hwts  = (const float*)d_in[15];
    const float* Wout  = (const float*)d_in[16];
    const float* bout  = (const float*)d_in[17];
    float* out = (float*)d_out;

    const int FUSED_SMEM = 24576 * 4;   // 98304 B
    const int OV_SMEM    = 18560 * 4;   // 74240 B
    cudaFuncSetAttribute(k_fused, cudaFuncAttributeMaxDynamicSharedMemorySize, FUSED_SMEM);
    cudaFuncSetAttribute(k_ov, cudaFuncAttributeMaxDynamicSharedMemorySize, OV_SMEM);

    k_gemm_proj<<<dim3(8, 24), 192>>>(s, Wq, bq, Wkv, bkv, Wqp, bqp, Wkvp, bkvp);
    k_scatter<<<NRES, 192>>>(rot, trans, hwts, mask);
    k_pre<<<dim3(8, 8, 12), 256>>>();
    k_fused<<<NRES, 512, FUSED_SMEM>>>(z, Wb, bb);
    k_ov<<<dim3(16, 12, 2), 320, OV_SMEM>>>();
    k_ovred<<<NRES, 192>>>(rot, trans);
    k_out<<<dim3(8, 8, 4), 192>>>(Wout);
    k_out_red<<<192, 256>>>(bout, out);
}

// round 9
// speedup vs baseline: 4.5623x; 1.1582x over previous
#include <cuda_runtime.h>
#include <math.h>

#define NRES 512
#define CS 384
#define CZ 128
#define CH 16
#define NH 12
#define PQ 4
#define PV 8

// ---------------- f32x2 packed-math helpers (sm_103a) ----------------
__device__ __forceinline__ unsigned long long dup2(float v) {
    unsigned long long r;
    asm("mov.b64 %0, {%1, %1};" : "=l"(r) : "f"(v));
    return r;
}
__device__ __forceinline__ void fma2(unsigned long long& d, unsigned long long a,
                                     unsigned long long b) {
    asm("fma.rn.f32x2 %0, %1, %2, %0;" : "+l"(d) : "l"(a), "l"(b));
}
__device__ __forceinline__ float2 upk2(unsigned long long v) {
    float2 f;
    asm("mov.b64 {%0, %1}, %2;" : "=f"(f.x), "=f"(f.y) : "l"(v));
    return f;
}

// ---------------- device scratch ----------------
__device__ __align__(16) float g_proj[NRES * 1152];           // q|kv|qp|kvp
__device__ __align__(16) float g_v2[NRES * NH * 40];          // [j][h][v(16)|vpts(24)]
__device__ __align__(16) float g_A[NH * NRES * 32];           // logit lhs
__device__ __align__(16) float g_B[NH * NRES * 32];           // logit rhs
__device__ __align__(16) float g_pre[(size_t)NH * NRES * NRES]; // [h][i][j] pre-logits
__device__ __align__(16) float g_a[(size_t)NH * NRES * NRES];   // [h][i][j] softmaxed
__device__ __align__(16) float g_ovp[2 * NRES * 480];         // j-split partials
__device__ __align__(16) float g_cat[NRES * 2112];
__device__ __align__(16) float g_opart[4 * NRES * 384];

// =============== K1: tiled GEMM, g_proj[512x1152] = s @ [Wq|Wkv|Wqp|Wkvp] ===============
__global__ void k_gemm_proj(const float* __restrict__ s,
                            const float* __restrict__ Wq, const float* __restrict__ bq,
                            const float* __restrict__ Wkv, const float* __restrict__ bkv,
                            const float* __restrict__ Wqp, const float* __restrict__ bqp,
                            const float* __restrict__ Wkvp, const float* __restrict__ bkvp) {
    __shared__ float s_sh[64 * 36];
    __shared__ float w_sh[32 * 48];
    int tid = threadIdx.x;            // 192
    int tx = tid % 12, ty = tid / 12;
    int r0 = blockIdx.x * 64;
    int by = blockIdx.y;

    const float* W; const float* bv; int outw, coff, gc0;
    if (by < 4)       { W = Wq;   bv = bq;   outw = 192; coff = 48 * by;        gc0 = coff; }
    else if (by < 12) { W = Wkv;  bv = bkv;  outw = 384; coff = 48 * (by - 4);  gc0 = 192 + coff; }
    else if (by < 15) { W = Wqp;  bv = bqp;  outw = 144; coff = 48 * (by - 12); gc0 = 576 + coff; }
    else              { W = Wkvp; bv = bkvp; outw = 432; coff = 48 * (by - 15); gc0 = 720 + coff; }

    ulonglong2 acc2[4];
    #pragma unroll
    for (int r = 0; r < 4; r++) { acc2[r].x = 0ULL; acc2[r].y = 0ULL; }

    for (int kt = 0; kt < 12; kt++) {
        int k0 = kt * 32;
        for (int idx = tid; idx < 512; idx += 192) {
            int r = idx >> 3, c4 = (idx & 7) << 2;
            *(float4*)&s_sh[r * 36 + c4] = *(const float4*)&s[(r0 + r) * 384 + k0 + c4];
        }
        for (int idx = tid; idx < 384; idx += 192) {
            int k = idx / 12, c4 = (idx % 12) << 2;
            *(float4*)&w_sh[k * 48 + c4] = *(const float4*)&W[(k0 + k) * outw + coff + c4];
        }
        __syncthreads();
        #pragma unroll 8
        for (int k = 0; k < 32; k++) {
            ulonglong2 b2 = *(const ulonglong2*)&w_sh[k * 48 + tx * 4];
            unsigned long long a0 = dup2(s_sh[(ty * 4 + 0) * 36 + k]);
            unsigned long long a1 = dup2(s_sh[(ty * 4 + 1) * 36 + k]);
            unsigned long long a2 = dup2(s_sh[(ty * 4 + 2) * 36 + k]);
            unsigned long long a3 = dup2(s_sh[(ty * 4 + 3) * 36 + k]);
            fma2(acc2[0].x, a0, b2.x); fma2(acc2[0].y, a0, b2.y);
            fma2(acc2[1].x, a1, b2.x); fma2(acc2[1].y, a1, b2.y);
            fma2(acc2[2].x, a2, b2.x); fma2(acc2[2].y, a2, b2.y);
            fma2(acc2[3].x, a3, b2.x); fma2(acc2[3].y, a3, b2.y);
        }
        __syncthreads();
    }
    float4 bbv = *(const float4*)&bv[coff + tx * 4];
    #pragma unroll
    for (int r = 0; r < 4; r++) {
        float2 lo = upk2(acc2[r].x), hi = upk2(acc2[r].y);
        float4 o;
        o.x = lo.x + bbv.x; o.y = lo.y + bbv.y;
        o.z = hi.x + bbv.z; o.w = hi.y + bbv.w;
        *(float4*)&g_proj[(r0 + ty * 4 + r) * 1152 + gc0 + tx * 4] = o;
    }
}

// =============== K2: scatter + frame transform + build A/B logit factors ===============
__global__ void k_scatter(const float* __restrict__ rot, const float* __restrict__ trans,
                          const float* __restrict__ hwts) {
    int i = blockIdx.x;
    int tid = threadIdx.x;  // 192
    __shared__ float sp_q[144];  // h*12 + p*3 + d
    __shared__ float sp_k[144];
    __shared__ float s_hw[12], s_q2[12], s_k2[12];
    const float* pr = &g_proj[i * 1152];

    if (tid < 12) {
        float x = hwts[tid];
        float sp = (x > 20.f) ? x : log1pf(expf(x));
        s_hw[tid] = sp * 0.13608276348795434f;  // softplus * sqrt(1/54)
    }
    float R[9], T[3];
    #pragma unroll
    for (int d = 0; d < 9; d++) R[d] = rot[i * 9 + d];
    #pragma unroll
    for (int d = 0; d < 3; d++) T[d] = trans[i * 3 + d];
    if (tid < 48) {  // q points: tid = h*4+p
        float pl[3];
        #pragma unroll
        for (int d = 0; d < 3; d++) pl[d] = pr[576 + d * 48 + tid];
        #pragma unroll
        for (int d = 0; d < 3; d++)
            sp_q[tid * 3 + d] = R[d * 3 + 0] * pl[0] + R[d * 3 + 1] * pl[1] + R[d * 3 + 2] * pl[2] + T[d];
    } else {         // kv points: idx = h*12+pp
        int idx = tid - 48; int h = idx / 12, pp = idx % 12;
        float pl[3];
        #pragma unroll
        for (int d = 0; d < 3; d++) pl[d] = pr[720 + d * 144 + idx];
        #pragma unroll
        for (int d = 0; d < 3; d++) {
            float g = R[d * 3 + 0] * pl[0] + R[d * 3 + 1] * pl[1] + R[d * 3 + 2] * pl[2] + T[d];
            if (pp < 4) sp_k[h * 12 + pp * 3 + d] = g;
            else        g_v2[i * 480 + h * 40 + 16 + (pp - 4) * 3 + d] = g;
        }
    }
    // v channels
    {
        int h = tid >> 4, c = tid & 15;
        g_v2[i * 480 + h * 40 + c] = pr[192 + h * 32 + 16 + c];
    }
    __syncthreads();
    if (tid < 12) {
        float sq = 0.f, sk = 0.f;
        #pragma unroll
        for (int t = 0; t < 12; t++) {
            float a = sp_q[tid * 12 + t]; sq += a * a;
            float b = sp_k[tid * 12 + t]; sk += b * b;
        }
        s_q2[tid] = sq; s_k2[tid] = sk;
    }
    __syncthreads();
    const float C1 = 0.14433756729740643f;  // sqrt(1/48)
    {
        int h = tid >> 4, c = tid & 15;
        g_A[(h * NRES + i) * 32 + c] = C1 * pr[h * 16 + c];
        g_B[(h * NRES + i) * 32 + c] = pr[192 + h * 32 + c];
    }
    if (tid < 144) {
        int h = tid / 12, t = tid % 12;
        g_A[(h * NRES + i) * 32 + 16 + t] = s_hw[h] * sp_q[h * 12 + t];
        g_B[(h * NRES + i) * 32 + 16 + t] = sp_k[h * 12 + t];
    }
    if (tid < 12) {
        int h = tid; float hw = s_hw[h];
        float* A = &g_A[(h * NRES + i) * 32];
        float* B = &g_B[(h * NRES + i) * 32];
        A[28] = -0.5f * hw * s_q2[h];  B[28] = 1.f;
        A[29] = 1.f;                   B[29] = -0.5f * hw * s_k2[h];
        A[30] = 0.f;                   B[30] = 0.f;   // mask handled exactly in k_fused
        A[31] = 0.f;                   B[31] = 0.f;
    }
}

// =============== K3: pre-logit GEMM g_pre[h][i][j] = A[h,i,:32] . B[h,j,:32] ===============
__global__ void k_pre() {  // grid (8 it, 8 jt, 12 h), 256 threads
    __shared__ float a_t[64 * 33];
    __shared__ float b_t[64 * 33];
    int h = blockIdx.z;
    int i0 = blockIdx.x * 64, j0 = blockIdx.y * 64;
    int tid = threadIdx.x;
    for (int f = tid; f < 512; f += 256) {
        int r = f >> 3, k4 = (f & 7) << 2;
        float4 v = *(const float4*)&g_A[(h * NRES + i0 + r) * 32 + k4];
        a_t[r * 33 + k4] = v.x; a_t[r * 33 + k4 + 1] = v.y;
        a_t[r * 33 + k4 + 2] = v.z; a_t[r * 33 + k4 + 3] = v.w;
        float4 w = *(const float4*)&g_B[(h * NRES + j0 + r) * 32 + k4];
        b_t[r * 33 + k4] = w.x; b_t[r * 33 + k4 + 1] = w.y;
        b_t[r * 33 + k4 + 2] = w.z; b_t[r * 33 + k4 + 3] = w.w;
    }
    __syncthreads();
    int tx = tid & 15, ty = tid >> 4;
    float acc[4][4];
    #pragma unroll
    for (int r = 0; r < 4; r++)
        #pragma unroll
        for (int u = 0; u < 4; u++) acc[r][u] = 0.f;
    #pragma unroll 8
    for (int k = 0; k < 32; k++) {
        float av[4], bv[4];
        #pragma unroll
        for (int r = 0; r < 4; r++) av[r] = a_t[(ty * 4 + r) * 33 + k];
        #pragma unroll
        for (int u = 0; u < 4; u++) bv[u] = b_t[(tx * 4 + u) * 33 + k];
        #pragma unroll
        for (int r = 0; r < 4; r++)
            #pragma unroll
            for (int u = 0; u < 4; u++) acc[r][u] += av[r] * bv[u];
    }
    #pragma unroll
    for (int r = 0; r < 4; r++) {
        float4 o = make_float4(acc[r][0], acc[r][1], acc[r][2], acc[r][3]);
        *(float4*)&g_pre[((size_t)h * NRES + i0 + ty * 4 + r) * NRES + j0 + tx * 4] = o;
    }
}

// =============== K4: fused bias + logits + softmax + o_pair, per residue i ===============
// smem: zc[128*132]=16896  av2[512*12]=6144  wbT[12*128]=1536  -> 24576 floats = 98304 B
__global__ __launch_bounds__(512) void k_fused(const float* __restrict__ z,
                                               const float* __restrict__ Wb,
                                               const float* __restrict__ bb,
                                               const float* __restrict__ mask) {
    extern __shared__ float sm[];
    float* zc  = sm;            // 16896: one 128-row j-chunk of z (132 stride pad)
    float* av2 = sm + 16896;    // 6144: [j][12]
    float* wbT = sm + 23040;    // 1536: [h][128]
    int i = blockIdx.x;
    int tid = threadIdx.x;      // 512
    int lane = tid & 31, wid = tid >> 5;

    for (int idx = tid; idx < 1536; idx += 512) {
        int h = idx >> 7, k = idx & 127;
        wbT[idx] = Wb[k * 12 + h];
    }

    // ---- phase A: av2[j][h] = z[i,j,:] . Wb[:,h]  (one thread per z-row) ----
    int my_chunk = tid >> 7;
    int jloc_a = tid & 127;
    for (int chunk = 0; chunk < 4; chunk++) {
        __syncthreads();
        for (int f = tid; f < 4096; f += 512) {
            int r = f >> 5, c4 = (f & 31) << 2;
            *(float4*)&zc[r * 132 + c4] =
                *(const float4*)&z[((size_t)(i * NRES) + chunk * 128 + r) * CZ + c4];
        }
        __syncthreads();
        if (my_chunk == chunk) {
            unsigned long long acc2[12];
            #pragma unroll
            for (int h = 0; h < 12; h++) acc2[h] = 0ULL;
            #pragma unroll 4
            for (int c4 = 0; c4 < 32; c4++) {
                ulonglong2 zv = *(const ulonglong2*)&zc[jloc_a * 132 + c4 * 4];
                #pragma unroll
                for (int h = 0; h < 12; h++) {
                    ulonglong2 wv = *(const ulonglong2*)&wbT[h * 128 + c4 * 4];
                    fma2(acc2[h], zv.x, wv.x);
                    fma2(acc2[h], zv.y, wv.y);
                }
            }
            int j = chunk * 128 + jloc_a;
            #pragma unroll
            for (int h = 0; h < 12; h++) {
                float2 p = upk2(acc2[h]);
                av2[j * 12 + h] = p.x + p.y;
            }
        }
    }
    __syncthreads();

    // ---- phase B: full logits (exact mask term) ----
    {
        int j = tid;
        float mterm = 100000.0f * (mask[i] * mask[j] - 1.0f);
        const float C2 = 0.5773502691896258f;  // sqrt(1/3)
        #pragma unroll
        for (int h = 0; h < 12; h++) {
            float lg = g_pre[((size_t)h * NRES + i) * NRES + j] +
                       C2 * (av2[j * 12 + h] + bb[h]) + mterm;
            av2[j * 12 + h] = lg;
        }
    }
    __syncthreads();

    // ---- phase C: softmax, one warp per head ----
    if (wid < 12) {
        int h = wid;
        float vals[16];
        float m = -3.4e38f;
        #pragma unroll
        for (int u = 0; u < 16; u++) {
            vals[u] = av2[(u * 32 + lane) * 12 + h];
            m = fmaxf(m, vals[u]);
        }
        #pragma unroll
        for (int off = 16; off > 0; off >>= 1) m = fmaxf(m, __shfl_xor_sync(0xffffffffu, m, off));
        float s = 0.f;
        #pragma unroll
        for (int u = 0; u < 16; u++) { vals[u] = __expf(vals[u] - m); s += vals[u]; }
        #pragma unroll
        for (int off = 16; off > 0; off >>= 1) s += __shfl_xor_sync(0xffffffffu, s, off);
        float inv = 1.0f / s;
        #pragma unroll
        for (int u = 0; u < 16; u++) {
            float an = vals[u] * inv;
            av2[(u * 32 + lane) * 12 + h] = an;
            g_a[((size_t)h * NRES + i) * NRES + u * 32 + lane] = an;
        }
    }
    __syncthreads();

    // ---- phase D: o_pair[h][c] = sum_j a[j][h] * z[i,j,c] ----
    // thread = (cgrp: 2 channels, jsub: 1/8 of j). Partials reduced via smem.
    int cgrp = tid & 63;   // channels cgrp*2, cgrp*2+1
    int jsub = tid >> 6;   // 0..7
    unsigned long long pacc[12];
    #pragma unroll
    for (int h = 0; h < 12; h++) pacc[h] = 0ULL;
    for (int chunk = 0; chunk < 4; chunk++) {
        __syncthreads();
        for (int f = tid; f < 4096; f += 512) {
            int r = f >> 5, c4 = (f & 31) << 2;
            *(float4*)&zc[r * 132 + c4] =
                *(const float4*)&z[((size_t)(i * NRES) + chunk * 128 + r) * CZ + c4];
        }
        __syncthreads();
        #pragma unroll 2
        for (int jj = 0; jj < 16; jj++) {
            int jloc = jsub * 16 + jj;
            int j = chunk * 128 + jloc;
            unsigned long long zv = *(const unsigned long long*)&zc[jloc * 132 + cgrp * 2];
            float4 a0 = *(const float4*)&av2[j * 12];
            float4 a1 = *(const float4*)&av2[j * 12 + 4];
            float4 a2 = *(const float4*)&av2[j * 12 + 8];
            fma2(pacc[0], dup2(a0.x), zv); fma2(pacc[1], dup2(a0.y), zv);
            fma2(pacc[2], dup2(a0.z), zv); fma2(pacc[3], dup2(a0.w), zv);
            fma2(pacc[4], dup2(a1.x), zv); fma2(pacc[5], dup2(a1.y), zv);
            fma2(pacc[6], dup2(a1.z), zv); fma2(pacc[7], dup2(a1.w), zv);
            fma2(pacc[8], dup2(a2.x), zv); fma2(pacc[9], dup2(a2.y), zv);
            fma2(pacc[10], dup2(a2.z), zv); fma2(pacc[11], dup2(a2.w), zv);
        }
    }
    // reduce 8 jsub partials per (h, channel): stage into zc[h*1024 + jsub*128 + c]
    __syncthreads();
    #pragma unroll
    for (int h = 0; h < 12; h++) {
        float2 p = upk2(pacc[h]);
        *(float2*)&zc[h * 1024 + jsub * 128 + cgrp * 2] = p;
    }
    __syncthreads();
    #pragma unroll
    for (int r = 0; r < 3; r++) {
        int idx = tid + 512 * r;     // 0..1535
        int h = idx >> 7, c = idx & 127;
        float ssum = 0.f;
        #pragma unroll
        for (int js = 0; js < 8; js++) ssum += zc[h * 1024 + js * 128 + c];
        g_cat[i * 2112 + 576 + h * 128 + c] = ssum;
    }
}

// =============== K5: o + o_pt GEMM, j-split partials ===============
// grid (16 i-tiles of 32, 12 h, 2 j-splits), 320 threads
__global__ void k_ov() {
    extern __shared__ float sm[];
    float* a_t  = sm;          // 32 * 260
    float* v2_t = sm + 8320;   // 256 * 40
    int i0 = blockIdx.x * 32;
    int h = blockIdx.y;
    int j0 = blockIdx.z * 256;
    int tid = threadIdx.x;
    for (int f = tid; f < 2048; f += 320) {
        int r = f >> 6, j4 = (f & 63) << 2;
        *(float4*)&a_t[r * 260 + j4] =
            *(const float4*)&g_a[((size_t)h * NRES + i0 + r) * NRES + j0 + j4];
    }
    for (int f = tid; f < 2560; f += 320) {
        int jj = f / 10, c4 = (f % 10) << 2;
        *(float4*)&v2_t[jj * 40 + c4] = *(const float4*)&g_v2[(j0 + jj) * 480 + h * 40 + c4];
    }
    __syncthreads();
    int row = tid & 31, cg = tid >> 5;  // cg 0..9
    ulonglong2 acc2; acc2.x = 0ULL; acc2.y = 0ULL;
    #pragma unroll 4
    for (int j4 = 0; j4 < 64; j4++) {
        float4 a4 = *(const float4*)&a_t[row * 260 + j4 * 4];
        ulonglong2 v0 = *(const ulonglong2*)&v2_t[(j4 * 4 + 0) * 40 + cg * 4];
        ulonglong2 v1 = *(const ulonglong2*)&v2_t[(j4 * 4 + 1) * 40 + cg * 4];
        ulonglong2 v2 = *(const ulonglong2*)&v2_t[(j4 * 4 + 2) * 40 + cg * 4];
        ulonglong2 v3 = *(const ulonglong2*)&v2_t[(j4 * 4 + 3) * 40 + cg * 4];
        unsigned long long d0 = dup2(a4.x), d1 = dup2(a4.y), d2 = dup2(a4.z), d3 = dup2(a4.w);
        fma2(acc2.x, d0, v0.x); fma2(acc2.y, d0, v0.y);
        fma2(acc2.x, d1, v1.x); fma2(acc2.y, d1, v1.y);
        fma2(acc2.x, d2, v2.x); fma2(acc2.y, d2, v2.y);
        fma2(acc2.x, d3, v3.x); fma2(acc2.y, d3, v3.y);
    }
    float2 lo = upk2(acc2.x), hi = upk2(acc2.y);
    float4 o = make_float4(lo.x, lo.y, hi.x, hi.y);
    *(float4*)&g_ovp[((size_t)blockIdx.z * NRES + i0 + row) * 480 + h * 40 + cg * 4] = o;
}

// =============== K6: reduce j-split partials + inverse frame + norms ===============
__global__ void k_ovred(const float* __restrict__ rot, const float* __restrict__ trans) {
    int i = blockIdx.x;
    int tid = threadIdx.x;  // 192
    {
        int h = tid >> 4, c = tid & 15;
        float v = g_ovp[(size_t)i * 480 + h * 40 + c] +
                  g_ovp[(size_t)(NRES + i) * 480 + h * 40 + c];
        g_cat[i * 2112 + tid] = v;
    }
    if (tid < 96) {
        int h = tid >> 3, p = tid & 7;
        float s0 = g_ovp[(size_t)i * 480 + h * 40 + 16 + p * 3 + 0] +
                   g_ovp[(size_t)(NRES + i) * 480 + h * 40 + 16 + p * 3 + 0];
        float s1 = g_ovp[(size_t)i * 480 + h * 40 + 16 + p * 3 + 1] +
                   g_ovp[(size_t)(NRES + i) * 480 + h * 40 + 16 + p * 3 + 1];
        float s2 = g_ovp[(size_t)i * 480 + h * 40 + 16 + p * 3 + 2] +
                   g_ovp[(size_t)(NRES + i) * 480 + h * 40 + 16 + p * 3 + 2];
        float g0 = s0 - trans[i * 3 + 0];
        float g1 = s1 - trans[i * 3 + 1];
        float g2 = s2 - trans[i * 3 + 2];
        float lx = rot[i * 9 + 0] * g0 + rot[i * 9 + 3] * g1 + rot[i * 9 + 6] * g2;
        float ly = rot[i * 9 + 1] * g0 + rot[i * 9 + 4] * g1 + rot[i * 9 + 7] * g2;
        float lz = rot[i * 9 + 2] * g0 + rot[i * 9 + 5] * g1 + rot[i * 9 + 8] * g2;
        float nrm = sqrtf(lx * lx + ly * ly + lz * lz + 1e-8f);
        g_cat[i * 2112 + 192 + tid] = lx;
        g_cat[i * 2112 + 288 + tid] = ly;
        g_cat[i * 2112 + 384 + tid] = lz;
        g_cat[i * 2112 + 480 + tid] = nrm;
    }
}

// =============== K7: split-K output GEMM (64x48 tiles, 4x4 micro, f32x2) ===============
__global__ void k_out(const float* __restrict__ Wout) {
    __shared__ float cat_s[64 * 48];
    __shared__ float w_s[48 * 48];
    int tid = threadIdx.x;             // 192
    int tx = tid % 12, ty = tid / 12;
    int i0 = blockIdx.x * 64;
    int c0 = blockIdx.y * 48;
    int ks = blockIdx.z;
    ulonglong2 acc2[4];
    #pragma unroll
    for (int r = 0; r < 4; r++) { acc2[r].x = 0ULL; acc2[r].y = 0ULL; }

    for (int kc = 0; kc < 11; kc++) {
        int k0 = ks * 528 + kc * 48;
        __syncthreads();
        for (int f = tid; f < 768; f += 192) {
            int r = f / 12, c4 = (f % 12) << 2;
            *(float4*)&cat_s[r * 48 + c4] = *(const float4*)&g_cat[(i0 + r) * 2112 + k0 + c4];
        }
        for (int f = tid; f < 576; f += 192) {
            int r = f / 12, c4 = (f % 12) << 2;
            *(float4*)&w_s[r * 48 + c4] = *(const float4*)&Wout[(k0 + r) * 384 + c0 + c4];
        }
        __syncthreads();
        #pragma unroll 8
        for (int k = 0; k < 48; k++) {
            ulonglong2 wv = *(const ulonglong2*)&w_s[k * 48 + tx * 4];
            unsigned long long a0 = dup2(cat_s[(ty * 4 + 0) * 48 + k]);
            unsigned long long a1 = dup2(cat_s[(ty * 4 + 1) * 48 + k]);
            unsigned long long a2 = dup2(cat_s[(ty * 4 + 2) * 48 + k]);
            unsigned long long a3 = dup2(cat_s[(ty * 4 + 3) * 48 + k]);
            fma2(acc2[0].x, a0, wv.x); fma2(acc2[0].y, a0, wv.y);
            fma2(acc2[1].x, a1, wv.x); fma2(acc2[1].y, a1, wv.y);
            fma2(acc2[2].x, a2, wv.x); fma2(acc2[2].y, a2, wv.y);
            fma2(acc2[3].x, a3, wv.x); fma2(acc2[3].y, a3, wv.y);
        }
    }
    #pragma unroll
    for (int r = 0; r < 4; r++) {
        float2 lo = upk2(acc2[r].x), hi = upk2(acc2[r].y);
        float4 o = make_float4(lo.x, lo.y, hi.x, hi.y);
        *(float4*)&g_opart[((size_t)ks * NRES + i0 + ty * 4 + r) * 384 + c0 + tx * 4] = o;
    }
}

__global__ void k_out_red(const float* __restrict__ bout, float* __restrict__ out) {
    int f = blockIdx.x * 256 + threadIdx.x;  // 49152 float4 jobs
    int i = f / 96;
    int c4 = (f % 96) * 4;
    float4 s0 = *(const float4*)&g_opart[(size_t)0 * 196608 + i * 384 + c4];
    float4 s1 = *(const float4*)&g_opart[(size_t)1 * 196608 + i * 384 + c4];
    float4 s2 = *(const float4*)&g_opart[(size_t)2 * 196608 + i * 384 + c4];
    float4 s3 = *(const float4*)&g_opart[(size_t)3 * 196608 + i * 384 + c4];
    float4 bv = *(const float4*)&bout[c4];
    float4 o;
    o.x = s0.x + s1.x + s2.x + s3.x + bv.x;
    o.y = s0.y + s1.y + s2.y + s3.y + bv.y;
    o.z = s0.z + s1.z + s2.z + s3.z + bv.z;
    o.w = s0.w + s1.w + s2.w + s3.w + bv.w;
    *(float4*)&out[i * 384 + c4] = o;
}

extern "C" void kernel_launch(void* const* d_in, const int* in_sizes, int n_in,
                              void* d_out, int out_size) {
    const float* s     = (const float*)d_in[0];
    const float* z     = (const float*)d_in[1];
    const float* rot   = (const float*)d_in[2];
    const float* trans = (const float*)d_in[3];
    const float* mask  = (const float*)d_in[4];
    const float* Wq    = (const float*)d_in[5];
    const float* bq    = (const float*)d_in[6];
    const float* Wkv   = (const float*)d_in[7];
    const float* bkv   = (const float*)d_in[8];
    const float* Wqp   = (const float*)d_in[9];
    const float* bqp   = (const float*)d_in[10];
    const float* Wkvp  = (const float*)d_in[11];
    const float* bkvp  = (const float*)d_in[12];
    const float* Wb    = (const float*)d_in[13];
    const float* bb    = (const float*)d_in[14];
    const float* hwts  = (const float*)d_in[15];
    const float* Wout  = (const float*)d_in[16];
    const float* bout  = (const float*)d_in[17];
    float* out = (float*)d_out;

    const int FUSED_SMEM = 24576 * 4;   // 98304 B
    const int OV_SMEM    = 18560 * 4;   // 74240 B
    cudaFuncSetAttribute(k_fused, cudaFuncAttributeMaxDynamicSharedMemorySize, FUSED_SMEM);
    cudaFuncSetAttribute(k_ov, cudaFuncAttributeMaxDynamicSharedMemorySize, OV_SMEM);

    k_gemm_proj<<<dim3(8, 24), 192>>>(s, Wq, bq, Wkv, bkv, Wqp, bqp, Wkvp, bkvp);
    k_scatter<<<NRES, 192>>>(rot, trans, hwts);
    k_pre<<<dim3(8, 8, 12), 256>>>();
    k_fused<<<NRES, 512, FUSED_SMEM>>>(z, Wb, bb, mask);
    k_ov<<<dim3(16, 12, 2), 320, OV_SMEM>>>();
    k_ovred<<<NRES, 192>>>(rot, trans);
    k_out<<<dim3(8, 8, 4), 192>>>(Wout);
    k_out_red<<<192, 256>>>(bout, out);
}